// round 1
// baseline (speedup 1.0000x reference)
#include <cuda_runtime.h>
#include <cstddef>

#define F 128
#define NPMAX 50000
#define NAMAX 100000

// ---------------- device scratch (no allocations allowed) ----------------
__device__ float g_agg_c[(size_t)NPMAX * F];
__device__ float g_agg_a[(size_t)NPMAX * F];
__device__ float g_agg_h[(size_t)NAMAX * F];
__device__ float g_p1[(size_t)NPMAX * F];
__device__ float g_a1[(size_t)NAMAX * F];
__device__ float g_p2[(size_t)NPMAX * F];
__device__ float g_inv_c[NPMAX];
__device__ float g_inv_a[NPMAX];
__device__ float g_inv_h[NAMAX];
__device__ float g_Wr1[F * F];
__device__ float g_Wr2[F * F];
__device__ float g_b1[F];
__device__ float g_b2[F];

// ---------------- degree counting ----------------
__global__ void count_kernel(const int* __restrict__ dst, float* __restrict__ cnt, int E) {
    int i = blockIdx.x * blockDim.x + threadIdx.x;
    if (i < E) atomicAdd(&cnt[dst[i]], 1.0f);
}

__global__ void invert_kernel(float* __restrict__ c, int n) {
    int i = blockIdx.x * blockDim.x + threadIdx.x;
    if (i < n) c[i] = 1.0f / fmaxf(c[i], 1.0f);
}

// ---------------- weight/bias pre-combination ----------------
__global__ void prep_kernel(const float* __restrict__ Wr1c, const float* __restrict__ Wr1a,
                            const float* __restrict__ b1c, const float* __restrict__ b1a,
                            const float* __restrict__ Wr2c, const float* __restrict__ Wr2a,
                            const float* __restrict__ b2c, const float* __restrict__ b2a) {
    int i = blockIdx.x * blockDim.x + threadIdx.x;
    if (i < F * F) {
        g_Wr1[i] = Wr1c[i] + Wr1a[i];
        g_Wr2[i] = Wr2c[i] + Wr2a[i];
    }
    if (i < F) {
        g_b1[i] = 0.5f * (b1c[i] + b1a[i]);
        g_b2[i] = 0.5f * (b2c[i] + b2a[i]);
    }
}

// ---------------- edge scatter-add: one warp per edge, vector atomics ----------------
__global__ void __launch_bounds__(256) scatter_kernel(const float* __restrict__ x,
                                                      const int* __restrict__ src,
                                                      const int* __restrict__ dst,
                                                      float* __restrict__ agg, int E) {
    int w = (blockIdx.x * blockDim.x + threadIdx.x) >> 5;
    int lane = threadIdx.x & 31;
    if (w >= E) return;
    int s = __ldg(&src[w]);
    int d = __ldg(&dst[w]);
    float4 v = *(const float4*)(x + (size_t)s * F + lane * 4);
    float* a = agg + (size_t)d * F + lane * 4;
    asm volatile("red.global.add.v4.f32 [%0], {%1,%2,%3,%4};"
                 :: "l"(a), "f"(v.x), "f"(v.y), "f"(v.z), "f"(v.w)
                 : "memory");
}

// ---------------- fused multi-source GEMM: C = act(alpha * sum_s (scale_s(m) * A_s @ W_s^T) + bias) ----------------
struct Src {
    const float* A;      // [M, 128]
    const float* scale;  // [M] per-row scale or nullptr
    const float* W;      // [128, 128] row-major W[n][k]
};

template <int NS, bool RELU>
__global__ void __launch_bounds__(256) gemm_kernel(Src s0, Src s1, Src s2,
                                                   const float* __restrict__ bias,
                                                   float alpha, float* __restrict__ C, int M) {
    __shared__ float As[64][36];    // [row][k] padded
    __shared__ float Ws[32][128];   // transposed: [k][n]
    Src srcs[3] = {s0, s1, s2};

    const int tid = threadIdx.x;
    const int tn = tid & 31;   // col quad: cols tn*4..tn*4+3
    const int tm = tid >> 5;   // row octet: rows tm*8..tm*8+7
    const int m0 = blockIdx.x * 64;

    float acc[8][4];
#pragma unroll
    for (int i = 0; i < 8; i++)
#pragma unroll
        for (int j = 0; j < 4; j++) acc[i][j] = 0.0f;

#pragma unroll
    for (int si = 0; si < NS; ++si) {
        const float* A = srcs[si].A;
        const float* scale = srcs[si].scale;
        const float* W = srcs[si].W;
        for (int k0 = 0; k0 < F; k0 += 32) {
            __syncthreads();
            // load A tile (pre-scaled by per-row factor, zero for OOB rows)
            {
                int r = tid >> 2;       // 0..63
                int kq = tid & 3;       // 0..3
                int m = m0 + r;
                float sc = 0.0f;
                int mr = 0;
                if (m < M) {
                    mr = m;
                    sc = scale ? scale[m] : 1.0f;
                }
                const float4* g = (const float4*)(A + (size_t)mr * F + k0);
                float4 v0 = g[kq];
                float4 v1 = g[kq + 4];
                v0.x *= sc; v0.y *= sc; v0.z *= sc; v0.w *= sc;
                v1.x *= sc; v1.y *= sc; v1.z *= sc; v1.w *= sc;
                *(float4*)&As[r][kq * 4] = v0;
                *(float4*)&As[r][kq * 4 + 16] = v1;
            }
            // load W tile transposed: Ws[k][n] = W[n][k0+k]
            {
                int n = tid >> 1;            // 0..127
                int kh = (tid & 1) * 16;     // 0 or 16
                const float* wr = W + n * F + k0 + kh;
#pragma unroll
                for (int j = 0; j < 16; j += 4) {
                    float4 v = *(const float4*)(wr + j);
                    Ws[kh + j + 0][n] = v.x;
                    Ws[kh + j + 1][n] = v.y;
                    Ws[kh + j + 2][n] = v.z;
                    Ws[kh + j + 3][n] = v.w;
                }
            }
            __syncthreads();
#pragma unroll
            for (int k = 0; k < 32; k++) {
                float4 w4 = *(const float4*)&Ws[k][tn * 4];
                float a[8];
#pragma unroll
                for (int i = 0; i < 8; i++) a[i] = As[tm * 8 + i][k];
#pragma unroll
                for (int i = 0; i < 8; i++) {
                    acc[i][0] = fmaf(a[i], w4.x, acc[i][0]);
                    acc[i][1] = fmaf(a[i], w4.y, acc[i][1]);
                    acc[i][2] = fmaf(a[i], w4.z, acc[i][2]);
                    acc[i][3] = fmaf(a[i], w4.w, acc[i][3]);
                }
            }
        }
    }

    float4 b4 = *(const float4*)(bias + tn * 4);
#pragma unroll
    for (int i = 0; i < 8; i++) {
        int m = m0 + tm * 8 + i;
        if (m < M) {
            float4 o;
            o.x = alpha * acc[i][0] + b4.x;
            o.y = alpha * acc[i][1] + b4.y;
            o.z = alpha * acc[i][2] + b4.z;
            o.w = alpha * acc[i][3] + b4.w;
            if (RELU) {
                o.x = fmaxf(o.x, 0.0f); o.y = fmaxf(o.y, 0.0f);
                o.z = fmaxf(o.z, 0.0f); o.w = fmaxf(o.w, 0.0f);
            }
            *(float4*)(C + (size_t)m * F + tn * 4) = o;
        }
    }
}

// ---------------- final classifier head: out[M,8] = p2 @ lin_W^T + b ----------------
__global__ void __launch_bounds__(256) head_kernel(const float* __restrict__ p2,
                                                   const float* __restrict__ W,
                                                   const float* __restrict__ b,
                                                   float* __restrict__ out, int M) {
    __shared__ float Ws[8 * F];
    int tid = threadIdx.x;
    *(float4*)&Ws[tid * 4] = *(const float4*)(W + tid * 4);  // 256*4 = 1024 = 8*128
    __syncthreads();
    int gid = blockIdx.x * 256 + tid;
    int m = gid >> 3;
    int c = gid & 7;
    if (m < M) {
        const float4* row = (const float4*)(p2 + (size_t)m * F);
        const float4* w = (const float4*)&Ws[c * F];
        float acc = 0.0f;
#pragma unroll
        for (int k = 0; k < 32; k++) {
            float4 a = row[k];
            float4 ww = w[k];
            acc = fmaf(a.x, ww.x, fmaf(a.y, ww.y, fmaf(a.z, ww.z, fmaf(a.w, ww.w, acc))));
        }
        out[gid] = acc + b[c];
    }
}

// ---------------- launch ----------------
extern "C" void kernel_launch(void* const* d_in, const int* in_sizes, int n_in,
                              void* d_out, int out_size) {
    const float* x_p    = (const float*)d_in[0];
    const float* x_a    = (const float*)d_in[1];
    const int*   c_src  = (const int*)d_in[2];
    const int*   c_dst  = (const int*)d_in[3];
    const int*   ao_src = (const int*)d_in[4];
    const int*   ao_dst = (const int*)d_in[5];
    const int*   ha_src = (const int*)d_in[6];
    const int*   ha_dst = (const int*)d_in[7];
    const float* l1c_Wl = (const float*)d_in[8];
    const float* l1c_bl = (const float*)d_in[9];
    const float* l1c_Wr = (const float*)d_in[10];
    const float* l1a_Wl = (const float*)d_in[11];
    const float* l1a_bl = (const float*)d_in[12];
    const float* l1a_Wr = (const float*)d_in[13];
    const float* l1h_Wl = (const float*)d_in[14];
    const float* l1h_bl = (const float*)d_in[15];
    const float* l1h_Wr = (const float*)d_in[16];
    const float* l2c_Wl = (const float*)d_in[17];
    const float* l2c_bl = (const float*)d_in[18];
    const float* l2c_Wr = (const float*)d_in[19];
    const float* l2a_Wl = (const float*)d_in[20];
    const float* l2a_bl = (const float*)d_in[21];
    const float* l2a_Wr = (const float*)d_in[22];
    // d_in[23..25] = l2h_* : dead code (author output of layer 2 never used)
    const float* lin_W  = (const float*)d_in[26];
    const float* lin_b  = (const float*)d_in[27];
    float* out = (float*)d_out;

    const int NP = in_sizes[0] / F;
    const int NA = in_sizes[1] / F;
    const int E  = in_sizes[2];

    float *agg_c, *agg_a, *agg_h, *p1, *a1, *p2;
    float *inv_c, *inv_a, *inv_h, *Wr1, *Wr2, *b1, *b2;
    cudaGetSymbolAddress((void**)&agg_c, g_agg_c);
    cudaGetSymbolAddress((void**)&agg_a, g_agg_a);
    cudaGetSymbolAddress((void**)&agg_h, g_agg_h);
    cudaGetSymbolAddress((void**)&p1, g_p1);
    cudaGetSymbolAddress((void**)&a1, g_a1);
    cudaGetSymbolAddress((void**)&p2, g_p2);
    cudaGetSymbolAddress((void**)&inv_c, g_inv_c);
    cudaGetSymbolAddress((void**)&inv_a, g_inv_a);
    cudaGetSymbolAddress((void**)&inv_h, g_inv_h);
    cudaGetSymbolAddress((void**)&Wr1, g_Wr1);
    cudaGetSymbolAddress((void**)&Wr2, g_Wr2);
    cudaGetSymbolAddress((void**)&b1, g_b1);
    cudaGetSymbolAddress((void**)&b2, g_b2);

    const int tb = 256;

    // zero degree accumulators + layer-1 aggregation buffers
    cudaMemsetAsync(inv_c, 0, (size_t)NP * sizeof(float), 0);
    cudaMemsetAsync(inv_a, 0, (size_t)NP * sizeof(float), 0);
    cudaMemsetAsync(inv_h, 0, (size_t)NA * sizeof(float), 0);
    cudaMemsetAsync(agg_c, 0, (size_t)NP * F * sizeof(float), 0);
    cudaMemsetAsync(agg_a, 0, (size_t)NP * F * sizeof(float), 0);
    cudaMemsetAsync(agg_h, 0, (size_t)NA * F * sizeof(float), 0);

    // degree counts -> inverse counts (reused by both layers)
    count_kernel<<<(E + tb - 1) / tb, tb>>>(c_dst, inv_c, E);
    count_kernel<<<(E + tb - 1) / tb, tb>>>(ao_dst, inv_a, E);
    count_kernel<<<(E + tb - 1) / tb, tb>>>(ha_dst, inv_h, E);
    invert_kernel<<<(NP + tb - 1) / tb, tb>>>(inv_c, NP);
    invert_kernel<<<(NP + tb - 1) / tb, tb>>>(inv_a, NP);
    invert_kernel<<<(NA + tb - 1) / tb, tb>>>(inv_h, NA);

    // pre-combine the two x_dst weight matrices per patent layer
    prep_kernel<<<(F * F + tb - 1) / tb, tb>>>(l1c_Wr, l1a_Wr, l1c_bl, l1a_bl,
                                               l2c_Wr, l2a_Wr, l2c_bl, l2a_bl);

    const int sblocks = (E + 7) / 8;  // one warp per edge, 8 warps/block

    // ---- layer 1 aggregations ----
    scatter_kernel<<<sblocks, tb>>>(x_p, c_src, c_dst, agg_c, E);
    scatter_kernel<<<sblocks, tb>>>(x_a, ao_src, ao_dst, agg_a, E);
    scatter_kernel<<<sblocks, tb>>>(x_p, ha_src, ha_dst, agg_h, E);

    // ---- layer 1 fused GEMMs ----
    Src sc{agg_c, inv_c, l1c_Wl};
    Src sa{agg_a, inv_a, l1a_Wl};
    Src sx{x_p, nullptr, Wr1};
    gemm_kernel<3, true><<<(NP + 63) / 64, 256>>>(sc, sa, sx, b1, 0.5f, p1, NP);

    Src sh{agg_h, inv_h, l1h_Wl};
    Src sxa{x_a, nullptr, l1h_Wr};
    gemm_kernel<2, true><<<(NA + 63) / 64, 256>>>(sh, sxa, sxa, l1h_bl, 1.0f, a1, NA);

    // ---- layer 2 aggregations (reuse buffers) ----
    cudaMemsetAsync(agg_c, 0, (size_t)NP * F * sizeof(float), 0);
    cudaMemsetAsync(agg_a, 0, (size_t)NP * F * sizeof(float), 0);
    scatter_kernel<<<sblocks, tb>>>(p1, c_src, c_dst, agg_c, E);
    scatter_kernel<<<sblocks, tb>>>(a1, ao_src, ao_dst, agg_a, E);

    // ---- layer 2 fused GEMM ----
    Src sc2{agg_c, inv_c, l2c_Wl};
    Src sa2{agg_a, inv_a, l2a_Wl};
    Src sp{p1, nullptr, Wr2};
    gemm_kernel<3, true><<<(NP + 63) / 64, 256>>>(sc2, sa2, sp, b2, 0.5f, p2, NP);

    // ---- classifier head ----
    head_kernel<<<(NP * 8 + tb - 1) / tb, tb>>>(p2, lin_W, lin_b, out, NP);
}

// round 4
// speedup vs baseline: 1.2205x; 1.2205x over previous
#include <cuda_runtime.h>
#include <cuda_bf16.h>
#include <cstdint>
#include <cstddef>

#define F 128
#define NPMAX 50000
#define NAMAX 100000

// ============================ helpers ============================
__device__ __forceinline__ uint32_t smem_u32(const void* p) {
    uint32_t a;
    asm("{ .reg .u64 t; cvta.to.shared.u64 t, %1; cvt.u32.u64 %0, t; }" : "=r"(a) : "l"(p));
    return a;
}
__device__ __forceinline__ void ldm_x4(uint32_t* r, uint32_t addr) {
    asm volatile("ldmatrix.sync.aligned.m8n8.x4.shared.b16 {%0,%1,%2,%3}, [%4];"
                 : "=r"(r[0]), "=r"(r[1]), "=r"(r[2]), "=r"(r[3]) : "r"(addr));
}
__device__ __forceinline__ void mma_bf16(float* c, const uint32_t* a, const uint32_t* b) {
    asm volatile(
        "mma.sync.aligned.m16n8k16.row.col.f32.bf16.bf16.f32 "
        "{%0,%1,%2,%3}, {%4,%5,%6,%7}, {%8,%9}, {%0,%1,%2,%3};"
        : "+f"(c[0]), "+f"(c[1]), "+f"(c[2]), "+f"(c[3])
        : "r"(a[0]), "r"(a[1]), "r"(a[2]), "r"(a[3]), "r"(b[0]), "r"(b[1]));
}

// [128 rows x 128 bf16] tile, 256B/row, 16B chunks, XOR swizzle chunk^(row&7)
__device__ __forceinline__ uint32_t tile_off(int row, int ch) {
    return (uint32_t)(row * 256 + ((ch ^ (row & 7)) << 4));
}

// ============================ device scratch ============================
__device__ float g_agg_c[(size_t)NPMAX * F];
__device__ float g_agg_a[(size_t)NPMAX * F];
__device__ float g_agg_h[(size_t)NAMAX * F];
__device__ float g_p1[(size_t)NPMAX * F];
__device__ float g_a1[(size_t)NAMAX * F];
__device__ float g_p2[(size_t)NPMAX * F];
__device__ float g_inv_c[NPMAX];
__device__ float g_inv_a[NPMAX];
__device__ float g_inv_h[NAMAX];
__device__ float g_b1[F];
__device__ float g_b2[F];
__device__ __nv_bfloat16 g_wblob[8][2][F * F];  // [matrix][hi/lo][tile-image layout]

// ============================ small kernels ============================
__global__ void count_kernel(const int* __restrict__ dst, float* __restrict__ cnt, int E) {
    int i = blockIdx.x * blockDim.x + threadIdx.x;
    if (i < E) atomicAdd(&cnt[dst[i]], 1.0f);
}
__global__ void invert_kernel(float* __restrict__ c, int n) {
    int i = blockIdx.x * blockDim.x + threadIdx.x;
    if (i < n) c[i] = 1.0f / fmaxf(c[i], 1.0f);
}
__global__ void prep_bias_kernel(const float* __restrict__ b1c, const float* __restrict__ b1a,
                                 const float* __restrict__ b2c, const float* __restrict__ b2a) {
    int i = threadIdx.x;
    if (i < F) {
        g_b1[i] = 0.5f * (b1c[i] + b1a[i]);
        g_b2[i] = 0.5f * (b2c[i] + b2a[i]);
    }
}

struct W8 { const float* a[8]; const float* b[8]; };

// Convert 8 weight matrices (optionally a+b summed) to bf16 hi/lo blobs in tile-image layout.
__global__ void prep_w_kernel(W8 w) {
    int mat = blockIdx.y;
    int ci = blockIdx.x * 256 + threadIdx.x;   // 0..2047, chunk of 8 elems
    if (ci >= 2048) return;
    int row = ci >> 4, ch = ci & 15;
    const float* pa = w.a[mat];
    const float* pb = w.b[mat];
    int base = row * F + ch * 8;
    uint32_t hi[4], lo[4];
#pragma unroll
    for (int j = 0; j < 4; j++) {
        float x0 = pa[base + 2 * j], x1 = pa[base + 2 * j + 1];
        if (pb) { x0 += pb[base + 2 * j]; x1 += pb[base + 2 * j + 1]; }
        __nv_bfloat16 h0 = __float2bfloat16_rn(x0);
        __nv_bfloat16 h1 = __float2bfloat16_rn(x1);
        __nv_bfloat16 l0 = __float2bfloat16_rn(x0 - __bfloat162float(h0));
        __nv_bfloat16 l1 = __float2bfloat16_rn(x1 - __bfloat162float(h1));
        hi[j] = ((uint32_t)__bfloat16_as_ushort(h1) << 16) | __bfloat16_as_ushort(h0);
        lo[j] = ((uint32_t)__bfloat16_as_ushort(l1) << 16) | __bfloat16_as_ushort(l0);
    }
    uint32_t o = tile_off(row, ch);
    *(uint4*)((char*)&g_wblob[mat][0][0] + o) = make_uint4(hi[0], hi[1], hi[2], hi[3]);
    *(uint4*)((char*)&g_wblob[mat][1][0] + o) = make_uint4(lo[0], lo[1], lo[2], lo[3]);
}

// ============================ edge scatter-add ============================
__global__ void __launch_bounds__(256) scatter_kernel(const float* __restrict__ x,
                                                      const int* __restrict__ src,
                                                      const int* __restrict__ dst,
                                                      float* __restrict__ agg, int E) {
    int w = (blockIdx.x * blockDim.x + threadIdx.x) >> 5;
    int lane = threadIdx.x & 31;
    if (w >= E) return;
    int s = __ldg(&src[w]);
    int d = __ldg(&dst[w]);
    float4 v = *(const float4*)(x + (size_t)s * F + lane * 4);
    float* a = agg + (size_t)d * F + lane * 4;
    asm volatile("red.global.add.v4.f32 [%0], {%1,%2,%3,%4};"
                 :: "l"(a), "f"(v.x), "f"(v.y), "f"(v.z), "f"(v.w) : "memory");
}

// ============================ mma.sync fused multi-source GEMM ============================
// C[M,128] = relu(alpha * sum_s scale_s(m) * A_s[M,128] @ W_s[128,128]^T + bias)
// split-bf16: A*W ~= Ahi*Whi + Ahi*Wlo + Alo*Whi, fp32 accumulate
struct GSrc {
    const float* A;
    const float* scale;             // per-row, or nullptr
    const __nv_bfloat16* whi;       // tile-image blobs, 32KB each
    const __nv_bfloat16* wlo;
};

#define SM_AHI 0
#define SM_ALO 32768
#define SM_WHI 65536
#define SM_WLO 98304
#define SM_TOTAL 131072

template <int NS>
__global__ void __launch_bounds__(256, 1) gemm_mma(GSrc s0, GSrc s1, GSrc s2,
                                                   const float* __restrict__ bias,
                                                   float alpha, float* __restrict__ C, int M) {
    extern __shared__ __align__(128) char smem[];
    uint32_t sbase = smem_u32(smem);
    const int tid = threadIdx.x;
    const int wid = tid >> 5;
    const int lane = tid & 31;
    const int warp_m = wid & 1;    // 2 x 64 rows
    const int warp_n = wid >> 1;   // 4 x 32 cols
    const int m0 = blockIdx.x * 128;
    GSrc srcs[3] = {s0, s1, s2};

    float acc[4][4][4];
#pragma unroll
    for (int i = 0; i < 4; i++)
#pragma unroll
        for (int j = 0; j < 4; j++)
#pragma unroll
            for (int k = 0; k < 4; k++) acc[i][j][k] = 0.0f;

    // ldmatrix per-lane address components.
    // A (non-trans x4): lanes 0-7 rows 0-7 ck0 | 8-15 rows 8-15 ck0 | 16-23 rows 0-7 ck1 | 24-31 rows 8-15 ck1
    const int a_row = warp_m * 64 + (lane & 15);                          // + mi*16
    const int a_cbase = (lane >> 4);                                      // + ks*2
    // W/B (non-trans x4): lanes 0-7 n-rows 0-7 ck0 | 8-15 n-rows 0-7 ck1 | 16-23 n-rows 8-15 ck0 | 24-31 n-rows 8-15 ck1
    const int w_row = warp_n * 32 + (lane & 7) + ((lane >> 4) << 3);      // + p*16
    const int w_cbase = (lane >> 3) & 1;                                  // + ks*2
    const int l7 = lane & 7;

#pragma unroll
    for (int si = 0; si < NS; si++) {
        __syncthreads();  // previous source's frags fully consumed
        // ---- copy W blobs (already tile-image layout) ----
        {
            const uint4* wh = (const uint4*)srcs[si].whi;
            const uint4* wl = (const uint4*)srcs[si].wlo;
            uint4* dh = (uint4*)(smem + SM_WHI);
            uint4* dl = (uint4*)(smem + SM_WLO);
#pragma unroll
            for (int i = tid; i < 2048; i += 256) { dh[i] = wh[i]; dl[i] = wl[i]; }
        }
        // ---- convert A tile fp32 -> bf16 hi/lo into swizzled SMEM ----
        {
            const float* A = srcs[si].A;
            const float* sc = srcs[si].scale;
#pragma unroll
            for (int ci = tid; ci < 2048; ci += 256) {
                int row = ci >> 4, ch = ci & 15;
                int m = m0 + row;
                float4 v0 = make_float4(0.f, 0.f, 0.f, 0.f), v1 = v0;
                float s = 0.f;
                if (m < M) {
                    s = sc ? __ldg(&sc[m]) : 1.0f;
                    const float4* g = (const float4*)(A + (size_t)m * F + ch * 8);
                    v0 = g[0]; v1 = g[1];
                }
                float vals[8] = {v0.x * s, v0.y * s, v0.z * s, v0.w * s,
                                 v1.x * s, v1.y * s, v1.z * s, v1.w * s};
                uint32_t hi[4], lo[4];
#pragma unroll
                for (int j = 0; j < 4; j++) {
                    __nv_bfloat16 h0 = __float2bfloat16_rn(vals[2 * j]);
                    __nv_bfloat16 h1 = __float2bfloat16_rn(vals[2 * j + 1]);
                    __nv_bfloat16 l0 = __float2bfloat16_rn(vals[2 * j] - __bfloat162float(h0));
                    __nv_bfloat16 l1 = __float2bfloat16_rn(vals[2 * j + 1] - __bfloat162float(h1));
                    hi[j] = ((uint32_t)__bfloat16_as_ushort(h1) << 16) | __bfloat16_as_ushort(h0);
                    lo[j] = ((uint32_t)__bfloat16_as_ushort(l1) << 16) | __bfloat16_as_ushort(l0);
                }
                uint32_t o = tile_off(row, ch);
                *(uint4*)(smem + SM_AHI + o) = make_uint4(hi[0], hi[1], hi[2], hi[3]);
                *(uint4*)(smem + SM_ALO + o) = make_uint4(lo[0], lo[1], lo[2], lo[3]);
            }
        }
        __syncthreads();

        // ---- MMA mainloop ----
#pragma unroll
        for (int ks = 0; ks < 8; ks++) {
            // W fragments: 4 n8-tiles via 2 x ldmatrix.x4 (NON-trans: W[n][k] row-major IS col-major B)
            uint32_t whi[4][2], wlo[4][2];
#pragma unroll
            for (int p = 0; p < 2; p++) {
                uint32_t woff = (uint32_t)(w_row + p * 16) * 256 +
                                (uint32_t)(((ks * 2 + w_cbase) ^ l7) << 4);
                uint32_t r[4];
                ldm_x4(r, sbase + SM_WHI + woff);
                whi[p * 2][0] = r[0]; whi[p * 2][1] = r[1];
                whi[p * 2 + 1][0] = r[2]; whi[p * 2 + 1][1] = r[3];
                ldm_x4(r, sbase + SM_WLO + woff);
                wlo[p * 2][0] = r[0]; wlo[p * 2][1] = r[1];
                wlo[p * 2 + 1][0] = r[2]; wlo[p * 2 + 1][1] = r[3];
            }
#pragma unroll
            for (int mi = 0; mi < 4; mi++) {
                uint32_t aoff = (uint32_t)(a_row + mi * 16) * 256 +
                                (uint32_t)(((ks * 2 + a_cbase) ^ l7) << 4);
                uint32_t ah[4], al[4];
                ldm_x4(ah, sbase + SM_AHI + aoff);
                ldm_x4(al, sbase + SM_ALO + aoff);
#pragma unroll
                for (int ni = 0; ni < 4; ni++) {
                    mma_bf16(acc[mi][ni], ah, whi[ni]);
                    mma_bf16(acc[mi][ni], ah, wlo[ni]);
                    mma_bf16(acc[mi][ni], al, whi[ni]);
                }
            }
        }
    }

    // ---- epilogue: alpha*acc + bias, relu, float2 stores ----
#pragma unroll
    for (int mi = 0; mi < 4; mi++) {
        int m = m0 + warp_m * 64 + mi * 16 + (lane >> 2);
#pragma unroll
        for (int ni = 0; ni < 4; ni++) {
            int n = warp_n * 32 + ni * 8 + (lane & 3) * 2;
            float b0 = __ldg(&bias[n]);
            float b1 = __ldg(&bias[n + 1]);
            if (m < M) {
                float2 o;
                o.x = fmaxf(fmaf(alpha, acc[mi][ni][0], b0), 0.f);
                o.y = fmaxf(fmaf(alpha, acc[mi][ni][1], b1), 0.f);
                *(float2*)(C + (size_t)m * F + n) = o;
            }
            if (m + 8 < M) {
                float2 o;
                o.x = fmaxf(fmaf(alpha, acc[mi][ni][2], b0), 0.f);
                o.y = fmaxf(fmaf(alpha, acc[mi][ni][3], b1), 0.f);
                *(float2*)(C + (size_t)(m + 8) * F + n) = o;
            }
        }
    }
}

// ============================ classifier head ============================
__global__ void __launch_bounds__(256) head_kernel(const float* __restrict__ p2,
                                                   const float* __restrict__ W,
                                                   const float* __restrict__ b,
                                                   float* __restrict__ out, int M) {
    __shared__ float Ws[8 * F];
    int tid = threadIdx.x;
    *(float4*)&Ws[tid * 4] = *(const float4*)(W + tid * 4);
    __syncthreads();
    int gid = blockIdx.x * 256 + tid;
    int m = gid >> 3;
    int c = gid & 7;
    if (m < M) {
        const float4* row = (const float4*)(p2 + (size_t)m * F);
        const float4* w = (const float4*)&Ws[c * F];
        float acc = 0.0f;
#pragma unroll
        for (int k = 0; k < 32; k++) {
            float4 a = row[k];
            float4 ww = w[k];
            acc = fmaf(a.x, ww.x, fmaf(a.y, ww.y, fmaf(a.z, ww.z, fmaf(a.w, ww.w, acc))));
        }
        out[gid] = acc + b[c];
    }
}

// ============================ launch ============================
extern "C" void kernel_launch(void* const* d_in, const int* in_sizes, int n_in,
                              void* d_out, int out_size) {
    const float* x_p    = (const float*)d_in[0];
    const float* x_a    = (const float*)d_in[1];
    const int*   c_src  = (const int*)d_in[2];
    const int*   c_dst  = (const int*)d_in[3];
    const int*   ao_src = (const int*)d_in[4];
    const int*   ao_dst = (const int*)d_in[5];
    const int*   ha_src = (const int*)d_in[6];
    const int*   ha_dst = (const int*)d_in[7];
    const float* l1c_Wl = (const float*)d_in[8];
    const float* l1c_bl = (const float*)d_in[9];
    const float* l1c_Wr = (const float*)d_in[10];
    const float* l1a_Wl = (const float*)d_in[11];
    const float* l1a_bl = (const float*)d_in[12];
    const float* l1a_Wr = (const float*)d_in[13];
    const float* l1h_Wl = (const float*)d_in[14];
    const float* l1h_bl = (const float*)d_in[15];
    const float* l1h_Wr = (const float*)d_in[16];
    const float* l2c_Wl = (const float*)d_in[17];
    const float* l2c_bl = (const float*)d_in[18];
    const float* l2c_Wr = (const float*)d_in[19];
    const float* l2a_Wl = (const float*)d_in[20];
    const float* l2a_bl = (const float*)d_in[21];
    const float* l2a_Wr = (const float*)d_in[22];
    const float* lin_W  = (const float*)d_in[26];
    const float* lin_b  = (const float*)d_in[27];
    float* out = (float*)d_out;

    const int NP = in_sizes[0] / F;
    const int NA = in_sizes[1] / F;
    const int E  = in_sizes[2];

    float *agg_c, *agg_a, *agg_h, *p1, *a1, *p2;
    float *inv_c, *inv_a, *inv_h, *b1, *b2;
    __nv_bfloat16* wblob;
    cudaGetSymbolAddress((void**)&agg_c, g_agg_c);
    cudaGetSymbolAddress((void**)&agg_a, g_agg_a);
    cudaGetSymbolAddress((void**)&agg_h, g_agg_h);
    cudaGetSymbolAddress((void**)&p1, g_p1);
    cudaGetSymbolAddress((void**)&a1, g_a1);
    cudaGetSymbolAddress((void**)&p2, g_p2);
    cudaGetSymbolAddress((void**)&inv_c, g_inv_c);
    cudaGetSymbolAddress((void**)&inv_a, g_inv_a);
    cudaGetSymbolAddress((void**)&inv_h, g_inv_h);
    cudaGetSymbolAddress((void**)&b1, g_b1);
    cudaGetSymbolAddress((void**)&b2, g_b2);
    cudaGetSymbolAddress((void**)&wblob, g_wblob);

    cudaFuncSetAttribute(gemm_mma<3>, cudaFuncAttributeMaxDynamicSharedMemorySize, SM_TOTAL);
    cudaFuncSetAttribute(gemm_mma<2>, cudaFuncAttributeMaxDynamicSharedMemorySize, SM_TOTAL);

    const int tb = 256;

    // zero degree accumulators + layer-1 aggregation buffers
    cudaMemsetAsync(inv_c, 0, (size_t)NP * sizeof(float), 0);
    cudaMemsetAsync(inv_a, 0, (size_t)NP * sizeof(float), 0);
    cudaMemsetAsync(inv_h, 0, (size_t)NA * sizeof(float), 0);
    cudaMemsetAsync(agg_c, 0, (size_t)NP * F * sizeof(float), 0);
    cudaMemsetAsync(agg_a, 0, (size_t)NP * F * sizeof(float), 0);
    cudaMemsetAsync(agg_h, 0, (size_t)NA * F * sizeof(float), 0);

    // degree counts -> inverse counts
    count_kernel<<<(E + tb - 1) / tb, tb>>>(c_dst, inv_c, E);
    count_kernel<<<(E + tb - 1) / tb, tb>>>(ao_dst, inv_a, E);
    count_kernel<<<(E + tb - 1) / tb, tb>>>(ha_dst, inv_h, E);
    invert_kernel<<<(NP + tb - 1) / tb, tb>>>(inv_c, NP);
    invert_kernel<<<(NP + tb - 1) / tb, tb>>>(inv_a, NP);
    invert_kernel<<<(NA + tb - 1) / tb, tb>>>(inv_h, NA);

    // bias combine + weight bf16 hi/lo blobs (tile-image layout)
    prep_bias_kernel<<<1, 128>>>(l1c_bl, l1a_bl, l2c_bl, l2a_bl);
    W8 w8;
    w8.a[0] = l1c_Wl; w8.b[0] = nullptr;
    w8.a[1] = l1a_Wl; w8.b[1] = nullptr;
    w8.a[2] = l1c_Wr; w8.b[2] = l1a_Wr;    // Wr1 = sum
    w8.a[3] = l1h_Wl; w8.b[3] = nullptr;
    w8.a[4] = l1h_Wr; w8.b[4] = nullptr;
    w8.a[5] = l2c_Wl; w8.b[5] = nullptr;
    w8.a[6] = l2a_Wl; w8.b[6] = nullptr;
    w8.a[7] = l2c_Wr; w8.b[7] = l2a_Wr;    // Wr2 = sum
    prep_w_kernel<<<dim3(8, 8), 256>>>(w8);

    const int sblocks = (E + 7) / 8;

    // ---- layer 1 aggregations ----
    scatter_kernel<<<sblocks, tb>>>(x_p, c_src, c_dst, agg_c, E);
    scatter_kernel<<<sblocks, tb>>>(x_a, ao_src, ao_dst, agg_a, E);
    scatter_kernel<<<sblocks, tb>>>(x_p, ha_src, ha_dst, agg_h, E);

    auto WB = [&](int m, int half) -> const __nv_bfloat16* {
        return wblob + ((size_t)m * 2 + half) * F * F;
    };

    // ---- layer 1 GEMMs (mma.sync) ----
    {
        GSrc sc{agg_c, inv_c, WB(0, 0), WB(0, 1)};
        GSrc sa{agg_a, inv_a, WB(1, 0), WB(1, 1)};
        GSrc sx{x_p, nullptr, WB(2, 0), WB(2, 1)};
        gemm_mma<3><<<(NP + 127) / 128, 256, SM_TOTAL>>>(sc, sa, sx, b1, 0.5f, p1, NP);
    }
    {
        GSrc sh{agg_h, inv_h, WB(3, 0), WB(3, 1)};
        GSrc sxa{x_a, nullptr, WB(4, 0), WB(4, 1)};
        gemm_mma<2><<<(NA + 127) / 128, 256, SM_TOTAL>>>(sh, sxa, sxa, l1h_bl, 1.0f, a1, NA);
    }

    // ---- layer 2 aggregations ----
    cudaMemsetAsync(agg_c, 0, (size_t)NP * F * sizeof(float), 0);
    cudaMemsetAsync(agg_a, 0, (size_t)NP * F * sizeof(float), 0);
    scatter_kernel<<<sblocks, tb>>>(p1, c_src, c_dst, agg_c, E);
    scatter_kernel<<<sblocks, tb>>>(a1, ao_src, ao_dst, agg_a, E);

    // ---- layer 2 GEMM ----
    {
        GSrc sc2{agg_c, inv_c, WB(5, 0), WB(5, 1)};
        GSrc sa2{agg_a, inv_a, WB(6, 0), WB(6, 1)};
        GSrc sp{p1, nullptr, WB(7, 0), WB(7, 1)};
        gemm_mma<3><<<(NP + 127) / 128, 256, SM_TOTAL>>>(sc2, sa2, sp, b2, 0.5f, p2, NP);
    }

    // ---- classifier head ----
    head_kernel<<<(NP * 8 + tb - 1) / tb, tb>>>(p2, lin_W, lin_b, out, NP);
}

// round 5
// speedup vs baseline: 1.5810x; 1.2954x over previous
#include <cuda_runtime.h>
#include <cuda_bf16.h>
#include <cstdint>
#include <cstddef>

#define F 128
#define NPMAX 50000
#define NAMAX 100000
#define EMAX 800000

// ============================ helpers ============================
__device__ __forceinline__ uint32_t smem_u32(const void* p) {
    uint32_t a;
    asm("{ .reg .u64 t; cvta.to.shared.u64 t, %1; cvt.u32.u64 %0, t; }" : "=r"(a) : "l"(p));
    return a;
}
__device__ __forceinline__ void ldm_x4(uint32_t* r, uint32_t addr) {
    asm volatile("ldmatrix.sync.aligned.m8n8.x4.shared.b16 {%0,%1,%2,%3}, [%4];"
                 : "=r"(r[0]), "=r"(r[1]), "=r"(r[2]), "=r"(r[3]) : "r"(addr));
}
__device__ __forceinline__ void mma_bf16(float* c, const uint32_t* a, const uint32_t* b) {
    asm volatile(
        "mma.sync.aligned.m16n8k16.row.col.f32.bf16.bf16.f32 "
        "{%0,%1,%2,%3}, {%4,%5,%6,%7}, {%8,%9}, {%0,%1,%2,%3};"
        : "+f"(c[0]), "+f"(c[1]), "+f"(c[2]), "+f"(c[3])
        : "r"(a[0]), "r"(a[1]), "r"(a[2]), "r"(a[3]), "r"(b[0]), "r"(b[1]));
}

// [128 rows x 128 bf16] tile, 256B/row, 16B chunks, XOR swizzle chunk^(row&7)
__device__ __forceinline__ uint32_t tile_off(int row, int ch) {
    return (uint32_t)(row * 256 + ((ch ^ (row & 7)) << 4));
}

// ============================ device scratch ============================
__device__ float g_agg_c[(size_t)NPMAX * F];
__device__ float g_agg_a[(size_t)NPMAX * F];
__device__ float g_agg_h[(size_t)NAMAX * F];
__device__ float g_p1[(size_t)NPMAX * F];
__device__ float g_a1[(size_t)NAMAX * F];
__device__ float g_p2[(size_t)NPMAX * F];
__device__ float g_b1[F];
__device__ float g_b2[F];
__device__ __nv_bfloat16 g_wblob[8][2][F * F];  // [matrix][hi/lo][tile-image layout]
// CSR structures (built once per launch, reused across layers)
__device__ int g_rp_c[NPMAX + 1];
__device__ int g_rp_a[NPMAX + 1];
__device__ int g_rp_h[NAMAX + 1];
__device__ int g_col_c[EMAX];
__device__ int g_col_a[EMAX];
__device__ int g_col_h[EMAX];
__device__ int g_cnt[NAMAX];
__device__ int g_cur[NAMAX];

// ============================ CSR build ============================
__global__ void count_kernel(const int* __restrict__ dst, int* __restrict__ cnt, int E) {
    int i = blockIdx.x * blockDim.x + threadIdx.x;
    if (i < E) atomicAdd(&cnt[dst[i]], 1);
}

// single-block exclusive scan: rp[0..n] from cnt[0..n-1]
__global__ void __launch_bounds__(1024) scan_kernel(const int* __restrict__ cnt,
                                                    int* __restrict__ rp, int n) {
    __shared__ int wsum[32];
    __shared__ int carry;
    int tid = threadIdx.x;
    int lane = tid & 31, warp = tid >> 5;
    if (tid == 0) carry = 0;
    __syncthreads();
    for (int base = 0; base < n; base += 1024) {
        int i = base + tid;
        int v = (i < n) ? cnt[i] : 0;
        int x = v;
#pragma unroll
        for (int o = 1; o < 32; o <<= 1) {
            int y = __shfl_up_sync(0xFFFFFFFF, x, o);
            if (lane >= o) x += y;
        }
        if (lane == 31) wsum[warp] = x;
        __syncthreads();
        if (tid < 32) {
            int y = wsum[tid];
            int z = y;
#pragma unroll
            for (int o = 1; o < 32; o <<= 1) {
                int t = __shfl_up_sync(0xFFFFFFFF, z, o);
                if (tid >= o) z += t;
            }
            wsum[tid] = z - y;  // exclusive warp offset
        }
        __syncthreads();
        int excl = carry + wsum[warp] + x - v;
        if (i < n) rp[i] = excl;
        __syncthreads();
        if (tid == 1023) carry = excl + v;
        __syncthreads();
    }
    if (tid == 0) rp[n] = carry;
}

__global__ void fill_kernel(const int* __restrict__ src, const int* __restrict__ dst,
                            const int* __restrict__ rp, int* __restrict__ cur,
                            int* __restrict__ col, int E) {
    int i = blockIdx.x * blockDim.x + threadIdx.x;
    if (i < E) {
        int d = dst[i];
        int p = atomicAdd(&cur[d], 1);
        col[rp[d] + p] = src[i];
    }
}

// ============================ CSR mean-gather: warp per dst node ============================
__global__ void __launch_bounds__(256) gather_kernel(const float* __restrict__ x,
                                                     const int* __restrict__ rp,
                                                     const int* __restrict__ col,
                                                     float* __restrict__ out, int n) {
    int w = (blockIdx.x * blockDim.x + threadIdx.x) >> 5;
    int lane = threadIdx.x & 31;
    if (w >= n) return;
    int s = __ldg(&rp[w]);
    int e = __ldg(&rp[w + 1]);
    float4 acc = make_float4(0.f, 0.f, 0.f, 0.f);
    for (int i = s; i < e; i++) {
        int c = __ldg(&col[i]);
        float4 v = *(const float4*)(x + (size_t)c * F + lane * 4);
        acc.x += v.x; acc.y += v.y; acc.z += v.z; acc.w += v.w;
    }
    float sc = 1.0f / fmaxf((float)(e - s), 1.0f);
    *(float4*)(out + (size_t)w * F + lane * 4) =
        make_float4(acc.x * sc, acc.y * sc, acc.z * sc, acc.w * sc);
}

// ============================ small kernels ============================
__global__ void prep_bias_kernel(const float* __restrict__ b1c, const float* __restrict__ b1a,
                                 const float* __restrict__ b2c, const float* __restrict__ b2a) {
    int i = threadIdx.x;
    if (i < F) {
        g_b1[i] = 0.5f * (b1c[i] + b1a[i]);
        g_b2[i] = 0.5f * (b2c[i] + b2a[i]);
    }
}

struct W8 { const float* a[8]; const float* b[8]; };

// Convert 8 weight matrices (optionally a+b summed) to bf16 hi/lo blobs in tile-image layout.
__global__ void prep_w_kernel(W8 w) {
    int mat = blockIdx.y;
    int ci = blockIdx.x * 256 + threadIdx.x;   // 0..2047, chunk of 8 elems
    if (ci >= 2048) return;
    int row = ci >> 4, ch = ci & 15;
    const float* pa = w.a[mat];
    const float* pb = w.b[mat];
    int base = row * F + ch * 8;
    uint32_t hi[4], lo[4];
#pragma unroll
    for (int j = 0; j < 4; j++) {
        float x0 = pa[base + 2 * j], x1 = pa[base + 2 * j + 1];
        if (pb) { x0 += pb[base + 2 * j]; x1 += pb[base + 2 * j + 1]; }
        __nv_bfloat16 h0 = __float2bfloat16_rn(x0);
        __nv_bfloat16 h1 = __float2bfloat16_rn(x1);
        __nv_bfloat16 l0 = __float2bfloat16_rn(x0 - __bfloat162float(h0));
        __nv_bfloat16 l1 = __float2bfloat16_rn(x1 - __bfloat162float(h1));
        hi[j] = ((uint32_t)__bfloat16_as_ushort(h1) << 16) | __bfloat16_as_ushort(h0);
        lo[j] = ((uint32_t)__bfloat16_as_ushort(l1) << 16) | __bfloat16_as_ushort(l0);
    }
    uint32_t o = tile_off(row, ch);
    *(uint4*)((char*)&g_wblob[mat][0][0] + o) = make_uint4(hi[0], hi[1], hi[2], hi[3]);
    *(uint4*)((char*)&g_wblob[mat][1][0] + o) = make_uint4(lo[0], lo[1], lo[2], lo[3]);
}

// ============================ mma.sync fused multi-source GEMM ============================
// C[M,128] = relu(alpha * sum_s A_s[M,128] @ W_s[128,128]^T + bias)
// split-bf16: A*W ~= Ahi*Whi + Ahi*Wlo + Alo*Whi, fp32 accumulate
struct GSrc {
    const float* A;
    const __nv_bfloat16* whi;       // tile-image blobs, 32KB each
    const __nv_bfloat16* wlo;
};

#define SM_AHI 0
#define SM_ALO 32768
#define SM_WHI 65536
#define SM_WLO 98304
#define SM_TOTAL 131072

template <int NS>
__global__ void __launch_bounds__(256, 1) gemm_mma(GSrc s0, GSrc s1, GSrc s2,
                                                   const float* __restrict__ bias,
                                                   float alpha, float* __restrict__ C, int M) {
    extern __shared__ __align__(128) char smem[];
    uint32_t sbase = smem_u32(smem);
    const int tid = threadIdx.x;
    const int wid = tid >> 5;
    const int lane = tid & 31;
    const int warp_m = wid & 1;    // 2 x 64 rows
    const int warp_n = wid >> 1;   // 4 x 32 cols
    const int m0 = blockIdx.x * 128;
    GSrc srcs[3] = {s0, s1, s2};

    float acc[4][4][4];
#pragma unroll
    for (int i = 0; i < 4; i++)
#pragma unroll
        for (int j = 0; j < 4; j++)
#pragma unroll
            for (int k = 0; k < 4; k++) acc[i][j][k] = 0.0f;

    const int a_row = warp_m * 64 + (lane & 15);
    const int a_cbase = (lane >> 4);
    const int w_row = warp_n * 32 + (lane & 7) + ((lane >> 4) << 3);
    const int w_cbase = (lane >> 3) & 1;
    const int l7 = lane & 7;

#pragma unroll
    for (int si = 0; si < NS; si++) {
        __syncthreads();
        // ---- copy W blobs (already tile-image layout) ----
        {
            const uint4* wh = (const uint4*)srcs[si].whi;
            const uint4* wl = (const uint4*)srcs[si].wlo;
            uint4* dh = (uint4*)(smem + SM_WHI);
            uint4* dl = (uint4*)(smem + SM_WLO);
#pragma unroll
            for (int i = tid; i < 2048; i += 256) { dh[i] = wh[i]; dl[i] = wl[i]; }
        }
        // ---- convert A tile fp32 -> bf16 hi/lo into swizzled SMEM ----
        {
            const float* A = srcs[si].A;
#pragma unroll
            for (int ci = tid; ci < 2048; ci += 256) {
                int row = ci >> 4, ch = ci & 15;
                int m = m0 + row;
                float4 v0 = make_float4(0.f, 0.f, 0.f, 0.f), v1 = v0;
                if (m < M) {
                    const float4* g = (const float4*)(A + (size_t)m * F + ch * 8);
                    v0 = g[0]; v1 = g[1];
                }
                float vals[8] = {v0.x, v0.y, v0.z, v0.w, v1.x, v1.y, v1.z, v1.w};
                uint32_t hi[4], lo[4];
#pragma unroll
                for (int j = 0; j < 4; j++) {
                    __nv_bfloat16 h0 = __float2bfloat16_rn(vals[2 * j]);
                    __nv_bfloat16 h1 = __float2bfloat16_rn(vals[2 * j + 1]);
                    __nv_bfloat16 l0 = __float2bfloat16_rn(vals[2 * j] - __bfloat162float(h0));
                    __nv_bfloat16 l1 = __float2bfloat16_rn(vals[2 * j + 1] - __bfloat162float(h1));
                    hi[j] = ((uint32_t)__bfloat16_as_ushort(h1) << 16) | __bfloat16_as_ushort(h0);
                    lo[j] = ((uint32_t)__bfloat16_as_ushort(l1) << 16) | __bfloat16_as_ushort(l0);
                }
                uint32_t o = tile_off(row, ch);
                *(uint4*)(smem + SM_AHI + o) = make_uint4(hi[0], hi[1], hi[2], hi[3]);
                *(uint4*)(smem + SM_ALO + o) = make_uint4(lo[0], lo[1], lo[2], lo[3]);
            }
        }
        __syncthreads();

        // ---- MMA mainloop ----
#pragma unroll
        for (int ks = 0; ks < 8; ks++) {
            uint32_t whi[4][2], wlo[4][2];
#pragma unroll
            for (int p = 0; p < 2; p++) {
                uint32_t woff = (uint32_t)(w_row + p * 16) * 256 +
                                (uint32_t)(((ks * 2 + w_cbase) ^ l7) << 4);
                uint32_t r[4];
                ldm_x4(r, sbase + SM_WHI + woff);
                whi[p * 2][0] = r[0]; whi[p * 2][1] = r[1];
                whi[p * 2 + 1][0] = r[2]; whi[p * 2 + 1][1] = r[3];
                ldm_x4(r, sbase + SM_WLO + woff);
                wlo[p * 2][0] = r[0]; wlo[p * 2][1] = r[1];
                wlo[p * 2 + 1][0] = r[2]; wlo[p * 2 + 1][1] = r[3];
            }
#pragma unroll
            for (int mi = 0; mi < 4; mi++) {
                uint32_t aoff = (uint32_t)(a_row + mi * 16) * 256 +
                                (uint32_t)(((ks * 2 + a_cbase) ^ l7) << 4);
                uint32_t ah[4], al[4];
                ldm_x4(ah, sbase + SM_AHI + aoff);
                ldm_x4(al, sbase + SM_ALO + aoff);
#pragma unroll
                for (int ni = 0; ni < 4; ni++) {
                    mma_bf16(acc[mi][ni], ah, whi[ni]);
                    mma_bf16(acc[mi][ni], ah, wlo[ni]);
                    mma_bf16(acc[mi][ni], al, whi[ni]);
                }
            }
        }
    }

    // ---- epilogue ----
#pragma unroll
    for (int mi = 0; mi < 4; mi++) {
        int m = m0 + warp_m * 64 + mi * 16 + (lane >> 2);
#pragma unroll
        for (int ni = 0; ni < 4; ni++) {
            int n = warp_n * 32 + ni * 8 + (lane & 3) * 2;
            float b0 = __ldg(&bias[n]);
            float b1 = __ldg(&bias[n + 1]);
            if (m < M) {
                float2 o;
                o.x = fmaxf(fmaf(alpha, acc[mi][ni][0], b0), 0.f);
                o.y = fmaxf(fmaf(alpha, acc[mi][ni][1], b1), 0.f);
                *(float2*)(C + (size_t)m * F + n) = o;
            }
            if (m + 8 < M) {
                float2 o;
                o.x = fmaxf(fmaf(alpha, acc[mi][ni][2], b0), 0.f);
                o.y = fmaxf(fmaf(alpha, acc[mi][ni][3], b1), 0.f);
                *(float2*)(C + (size_t)(m + 8) * F + n) = o;
            }
        }
    }
}

// ============================ classifier head ============================
__global__ void __launch_bounds__(256) head_kernel(const float* __restrict__ p2,
                                                   const float* __restrict__ W,
                                                   const float* __restrict__ b,
                                                   float* __restrict__ out, int M) {
    __shared__ float Ws[8 * F];
    int tid = threadIdx.x;
    *(float4*)&Ws[tid * 4] = *(const float4*)(W + tid * 4);
    __syncthreads();
    int gid = blockIdx.x * 256 + tid;
    int m = gid >> 3;
    int c = gid & 7;
    if (m < M) {
        const float4* row = (const float4*)(p2 + (size_t)m * F);
        const float4* w = (const float4*)&Ws[c * F];
        float acc = 0.0f;
#pragma unroll
        for (int k = 0; k < 32; k++) {
            float4 a = row[k];
            float4 ww = w[k];
            acc = fmaf(a.x, ww.x, fmaf(a.y, ww.y, fmaf(a.z, ww.z, fmaf(a.w, ww.w, acc))));
        }
        out[gid] = acc + b[c];
    }
}

// ============================ launch ============================
extern "C" void kernel_launch(void* const* d_in, const int* in_sizes, int n_in,
                              void* d_out, int out_size) {
    const float* x_p    = (const float*)d_in[0];
    const float* x_a    = (const float*)d_in[1];
    const int*   c_src  = (const int*)d_in[2];
    const int*   c_dst  = (const int*)d_in[3];
    const int*   ao_src = (const int*)d_in[4];
    const int*   ao_dst = (const int*)d_in[5];
    const int*   ha_src = (const int*)d_in[6];
    const int*   ha_dst = (const int*)d_in[7];
    const float* l1c_Wl = (const float*)d_in[8];
    const float* l1c_bl = (const float*)d_in[9];
    const float* l1c_Wr = (const float*)d_in[10];
    const float* l1a_Wl = (const float*)d_in[11];
    const float* l1a_bl = (const float*)d_in[12];
    const float* l1a_Wr = (const float*)d_in[13];
    const float* l1h_Wl = (const float*)d_in[14];
    const float* l1h_bl = (const float*)d_in[15];
    const float* l1h_Wr = (const float*)d_in[16];
    const float* l2c_Wl = (const float*)d_in[17];
    const float* l2c_bl = (const float*)d_in[18];
    const float* l2c_Wr = (const float*)d_in[19];
    const float* l2a_Wl = (const float*)d_in[20];
    const float* l2a_bl = (const float*)d_in[21];
    const float* l2a_Wr = (const float*)d_in[22];
    const float* lin_W  = (const float*)d_in[26];
    const float* lin_b  = (const float*)d_in[27];
    float* out = (float*)d_out;

    const int NP = in_sizes[0] / F;
    const int NA = in_sizes[1] / F;
    const int E  = in_sizes[2];

    float *agg_c, *agg_a, *agg_h, *p1, *a1, *p2, *b1, *b2;
    int *rp_c, *rp_a, *rp_h, *col_c, *col_a, *col_h, *cnt, *cur;
    __nv_bfloat16* wblob;
    cudaGetSymbolAddress((void**)&agg_c, g_agg_c);
    cudaGetSymbolAddress((void**)&agg_a, g_agg_a);
    cudaGetSymbolAddress((void**)&agg_h, g_agg_h);
    cudaGetSymbolAddress((void**)&p1, g_p1);
    cudaGetSymbolAddress((void**)&a1, g_a1);
    cudaGetSymbolAddress((void**)&p2, g_p2);
    cudaGetSymbolAddress((void**)&b1, g_b1);
    cudaGetSymbolAddress((void**)&b2, g_b2);
    cudaGetSymbolAddress((void**)&wblob, g_wblob);
    cudaGetSymbolAddress((void**)&rp_c, g_rp_c);
    cudaGetSymbolAddress((void**)&rp_a, g_rp_a);
    cudaGetSymbolAddress((void**)&rp_h, g_rp_h);
    cudaGetSymbolAddress((void**)&col_c, g_col_c);
    cudaGetSymbolAddress((void**)&col_a, g_col_a);
    cudaGetSymbolAddress((void**)&col_h, g_col_h);
    cudaGetSymbolAddress((void**)&cnt, g_cnt);
    cudaGetSymbolAddress((void**)&cur, g_cur);

    cudaFuncSetAttribute(gemm_mma<3>, cudaFuncAttributeMaxDynamicSharedMemorySize, SM_TOTAL);
    cudaFuncSetAttribute(gemm_mma<2>, cudaFuncAttributeMaxDynamicSharedMemorySize, SM_TOTAL);

    const int tb = 256;
    const int eb = (E + tb - 1) / tb;

    // ---- weight prep ----
    prep_bias_kernel<<<1, 128>>>(l1c_bl, l1a_bl, l2c_bl, l2a_bl);
    W8 w8;
    w8.a[0] = l1c_Wl; w8.b[0] = nullptr;
    w8.a[1] = l1a_Wl; w8.b[1] = nullptr;
    w8.a[2] = l1c_Wr; w8.b[2] = l1a_Wr;    // Wr1 = sum
    w8.a[3] = l1h_Wl; w8.b[3] = nullptr;
    w8.a[4] = l1h_Wr; w8.b[4] = nullptr;
    w8.a[5] = l2c_Wl; w8.b[5] = nullptr;
    w8.a[6] = l2a_Wl; w8.b[6] = nullptr;
    w8.a[7] = l2c_Wr; w8.b[7] = l2a_Wr;    // Wr2 = sum
    prep_w_kernel<<<dim3(8, 8), 256>>>(w8);

    // ---- CSR build (3 relations, reused across both layers) ----
    auto build_csr = [&](const int* src, const int* dst, int* rp, int* col, int n) {
        cudaMemsetAsync(cnt, 0, (size_t)n * sizeof(int), 0);
        count_kernel<<<eb, tb>>>(dst, cnt, E);
        scan_kernel<<<1, 1024>>>(cnt, rp, n);
        cudaMemsetAsync(cur, 0, (size_t)n * sizeof(int), 0);
        fill_kernel<<<eb, tb>>>(src, dst, rp, cur, col, E);
    };
    build_csr(c_src, c_dst, rp_c, col_c, NP);
    build_csr(ao_src, ao_dst, rp_a, col_a, NP);
    build_csr(ha_src, ha_dst, rp_h, col_h, NA);

    const int gb_p = (NP * 32 + tb - 1) / tb;   // warp per node
    const int gb_a = (NA * 32 + tb - 1) / tb;

    // ---- layer 1 mean-gathers ----
    gather_kernel<<<gb_p, tb>>>(x_p, rp_c, col_c, agg_c, NP);
    gather_kernel<<<gb_p, tb>>>(x_a, rp_a, col_a, agg_a, NP);
    gather_kernel<<<gb_a, tb>>>(x_p, rp_h, col_h, agg_h, NA);

    auto WB = [&](int m, int half) -> const __nv_bfloat16* {
        return wblob + ((size_t)m * 2 + half) * F * F;
    };

    // ---- layer 1 GEMMs ----
    {
        GSrc sc{agg_c, WB(0, 0), WB(0, 1)};
        GSrc sa{agg_a, WB(1, 0), WB(1, 1)};
        GSrc sx{x_p, WB(2, 0), WB(2, 1)};
        gemm_mma<3><<<(NP + 127) / 128, 256, SM_TOTAL>>>(sc, sa, sx, b1, 0.5f, p1, NP);
    }
    {
        GSrc sh{agg_h, WB(3, 0), WB(3, 1)};
        GSrc sxa{x_a, WB(4, 0), WB(4, 1)};
        gemm_mma<2><<<(NA + 127) / 128, 256, SM_TOTAL>>>(sh, sxa, sxa, l1h_bl, 1.0f, a1, NA);
    }

    // ---- layer 2 mean-gathers (reuse CSR) ----
    gather_kernel<<<gb_p, tb>>>(p1, rp_c, col_c, agg_c, NP);
    gather_kernel<<<gb_p, tb>>>(a1, rp_a, col_a, agg_a, NP);

    // ---- layer 2 GEMM ----
    {
        GSrc sc2{agg_c, WB(5, 0), WB(5, 1)};
        GSrc sa2{agg_a, WB(6, 0), WB(6, 1)};
        GSrc sp{p1, WB(7, 0), WB(7, 1)};
        gemm_mma<3><<<(NP + 127) / 128, 256, SM_TOTAL>>>(sc2, sa2, sp, b2, 0.5f, p2, NP);
    }

    // ---- classifier head ----
    head_kernel<<<(NP * 8 + tb - 1) / tb, tb>>>(p2, lin_W, lin_b, out, NP);
}

// round 6
// speedup vs baseline: 2.1062x; 1.3322x over previous
#include <cuda_runtime.h>
#include <cuda_bf16.h>
#include <cstdint>
#include <cstddef>

#define F 128
#define NPMAX 50000
#define NAMAX 100000
#define EMAX 800000
#define N3MAX (2 * NPMAX + NAMAX)

// ============================ helpers ============================
__device__ __forceinline__ uint32_t smem_u32(const void* p) {
    uint32_t a;
    asm("{ .reg .u64 t; cvta.to.shared.u64 t, %1; cvt.u32.u64 %0, t; }" : "=r"(a) : "l"(p));
    return a;
}
__device__ __forceinline__ void ldm_x4(uint32_t* r, uint32_t addr) {
    asm volatile("ldmatrix.sync.aligned.m8n8.x4.shared.b16 {%0,%1,%2,%3}, [%4];"
                 : "=r"(r[0]), "=r"(r[1]), "=r"(r[2]), "=r"(r[3]) : "r"(addr));
}
__device__ __forceinline__ void mma_bf16(float* c, const uint32_t* a, const uint32_t* b) {
    asm volatile(
        "mma.sync.aligned.m16n8k16.row.col.f32.bf16.bf16.f32 "
        "{%0,%1,%2,%3}, {%4,%5,%6,%7}, {%8,%9}, {%0,%1,%2,%3};"
        : "+f"(c[0]), "+f"(c[1]), "+f"(c[2]), "+f"(c[3])
        : "r"(a[0]), "r"(a[1]), "r"(a[2]), "r"(a[3]), "r"(b[0]), "r"(b[1]));
}

// [128 rows x 128 bf16] tile, 256B/row, 16B chunks, XOR swizzle chunk^(row&7)
__device__ __forceinline__ uint32_t tile_off(int row, int ch) {
    return (uint32_t)(row * 256 + ((ch ^ (row & 7)) << 4));
}

// ============================ device scratch ============================
__device__ float g_agg_c[(size_t)NPMAX * F];
__device__ float g_agg_a[(size_t)NPMAX * F];
__device__ float g_agg_h[(size_t)NAMAX * F];
__device__ float g_p1[(size_t)NPMAX * F];
__device__ float g_a1[(size_t)NAMAX * F];
__device__ float g_p2[(size_t)NPMAX * F];
__device__ float g_b1[F];
__device__ float g_b2[F];
__device__ __nv_bfloat16 g_wblob[8][2][F * F];  // [matrix][hi/lo][tile-image layout]
// fused CSR over 3 relations: segments [0,NP) c | [NP,2NP) a | [2NP,2NP+NA) h
__device__ int g_cnt3[N3MAX];
__device__ int g_cur3[N3MAX];
__device__ int g_rp3[N3MAX + 1];
__device__ int g_col3[3 * EMAX];
__device__ int g_part[128];

// ============================ fused CSR build ============================
__global__ void count3_kernel(const int* __restrict__ cd, const int* __restrict__ ad,
                              const int* __restrict__ hd, int* __restrict__ cnt3,
                              int E, int NP) {
    int i = blockIdx.x * blockDim.x + threadIdx.x;
    if (i < E) atomicAdd(&cnt3[cd[i]], 1);
    else if (i < 2 * E) atomicAdd(&cnt3[NP + ad[i - E]], 1);
    else if (i < 3 * E) atomicAdd(&cnt3[2 * NP + hd[i - 2 * E]], 1);
}

// pass A: per-block (2048-elem chunk) sums
__global__ void __launch_bounds__(1024) scanA_kernel(const int* __restrict__ cnt,
                                                     int* __restrict__ part, int n) {
    __shared__ int wsum[32];
    int tid = threadIdx.x;
    int base = blockIdx.x * 2048 + tid * 2;
    int v = 0;
    if (base < n) v += cnt[base];
    if (base + 1 < n) v += cnt[base + 1];
#pragma unroll
    for (int o = 16; o; o >>= 1) v += __shfl_down_sync(0xFFFFFFFF, v, o);
    if ((tid & 31) == 0) wsum[tid >> 5] = v;
    __syncthreads();
    if (tid < 32) {
        int x = wsum[tid];
#pragma unroll
        for (int o = 16; o; o >>= 1) x += __shfl_down_sync(0xFFFFFFFF, x, o);
        if (tid == 0) part[blockIdx.x] = x;
    }
}

// pass B: exclusive-scan <=128 partials in one block; also writes total to rp_end
__global__ void scanB_kernel(int* __restrict__ part, int* __restrict__ rp_end, int nb) {
    __shared__ int ws[4];
    int tid = threadIdx.x;     // 128 threads
    int lane = tid & 31, w = tid >> 5;
    int v = (tid < nb) ? part[tid] : 0;
    int x = v;
#pragma unroll
    for (int o = 1; o < 32; o <<= 1) {
        int y = __shfl_up_sync(0xFFFFFFFF, x, o);
        if (lane >= o) x += y;
    }
    if (lane == 31) ws[w] = x;
    __syncthreads();
    int add = 0;
#pragma unroll
    for (int i = 0; i < 4; i++) add += (i < w) ? ws[i] : 0;
    x += add;
    if (tid < nb) part[tid] = x - v;   // exclusive block offset
    if (tid == 127) *rp_end = x;       // grand total
}

// pass C: rescan chunk with block offset, write exclusive rp
__global__ void __launch_bounds__(1024) scanC_kernel(const int* __restrict__ cnt,
                                                     const int* __restrict__ part,
                                                     int* __restrict__ rp, int n) {
    __shared__ int woff[32];
    int tid = threadIdx.x;
    int lane = tid & 31, w = tid >> 5;
    int base = blockIdx.x * 2048 + tid * 2;
    int e0 = (base < n) ? cnt[base] : 0;
    int e1 = (base + 1 < n) ? cnt[base + 1] : 0;
    int p = e0 + e1;
    int x = p;
#pragma unroll
    for (int o = 1; o < 32; o <<= 1) {
        int y = __shfl_up_sync(0xFFFFFFFF, x, o);
        if (lane >= o) x += y;
    }
    if (lane == 31) woff[w] = x;
    __syncthreads();
    if (tid < 32) {
        int y = woff[tid];
        int z = y;
#pragma unroll
        for (int o = 1; o < 32; o <<= 1) {
            int t = __shfl_up_sync(0xFFFFFFFF, z, o);
            if (tid >= o) z += t;
        }
        woff[tid] = z - y;
    }
    __syncthreads();
    int off = part[blockIdx.x] + woff[w] + x - p;   // exclusive for this thread
    if (base < n) rp[base] = off;
    if (base + 1 < n) rp[base + 1] = off + e0;
}

__global__ void fill3_kernel(const int* __restrict__ cs, const int* __restrict__ cd,
                             const int* __restrict__ as, const int* __restrict__ ad,
                             const int* __restrict__ hs, const int* __restrict__ hd,
                             const int* __restrict__ rp3, int* __restrict__ cur3,
                             int* __restrict__ col3, int E, int NP) {
    int i = blockIdx.x * blockDim.x + threadIdx.x;
    int s, d;
    if (i < E) { s = cs[i]; d = cd[i]; }
    else if (i < 2 * E) { s = as[i - E]; d = NP + ad[i - E]; }
    else if (i < 3 * E) { s = hs[i - 2 * E]; d = 2 * NP + hd[i - 2 * E]; }
    else return;
    int p = atomicAdd(&cur3[d], 1);
    col3[rp3[d] + p] = s;
}

// ============================ CSR mean-gather: warp per dst node ============================
__global__ void __launch_bounds__(256) gather_kernel(const float* __restrict__ x,
                                                     const int* __restrict__ rp,
                                                     const int* __restrict__ col,
                                                     float* __restrict__ out, int n) {
    int w = (blockIdx.x * blockDim.x + threadIdx.x) >> 5;
    int lane = threadIdx.x & 31;
    if (w >= n) return;
    int s = __ldg(&rp[w]);
    int e = __ldg(&rp[w + 1]);
    float4 acc = make_float4(0.f, 0.f, 0.f, 0.f);
    for (int i = s; i < e; i++) {
        int c = __ldg(&col[i]);
        float4 v = *(const float4*)(x + (size_t)c * F + lane * 4);
        acc.x += v.x; acc.y += v.y; acc.z += v.z; acc.w += v.w;
    }
    float sc = 1.0f / fmaxf((float)(e - s), 1.0f);
    *(float4*)(out + (size_t)w * F + lane * 4) =
        make_float4(acc.x * sc, acc.y * sc, acc.z * sc, acc.w * sc);
}

// ============================ small kernels ============================
__global__ void prep_bias_kernel(const float* __restrict__ b1c, const float* __restrict__ b1a,
                                 const float* __restrict__ b2c, const float* __restrict__ b2a) {
    int i = threadIdx.x;
    if (i < F) {
        g_b1[i] = 0.5f * (b1c[i] + b1a[i]);
        g_b2[i] = 0.5f * (b2c[i] + b2a[i]);
    }
}

struct W8 { const float* a[8]; const float* b[8]; };

__global__ void prep_w_kernel(W8 w) {
    int mat = blockIdx.y;
    int ci = blockIdx.x * 256 + threadIdx.x;   // 0..2047, chunk of 8 elems
    if (ci >= 2048) return;
    int row = ci >> 4, ch = ci & 15;
    const float* pa = w.a[mat];
    const float* pb = w.b[mat];
    int base = row * F + ch * 8;
    uint32_t hi[4], lo[4];
#pragma unroll
    for (int j = 0; j < 4; j++) {
        float x0 = pa[base + 2 * j], x1 = pa[base + 2 * j + 1];
        if (pb) { x0 += pb[base + 2 * j]; x1 += pb[base + 2 * j + 1]; }
        __nv_bfloat16 h0 = __float2bfloat16_rn(x0);
        __nv_bfloat16 h1 = __float2bfloat16_rn(x1);
        __nv_bfloat16 l0 = __float2bfloat16_rn(x0 - __bfloat162float(h0));
        __nv_bfloat16 l1 = __float2bfloat16_rn(x1 - __bfloat162float(h1));
        hi[j] = ((uint32_t)__bfloat16_as_ushort(h1) << 16) | __bfloat16_as_ushort(h0);
        lo[j] = ((uint32_t)__bfloat16_as_ushort(l1) << 16) | __bfloat16_as_ushort(l0);
    }
    uint32_t o = tile_off(row, ch);
    *(uint4*)((char*)&g_wblob[mat][0][0] + o) = make_uint4(hi[0], hi[1], hi[2], hi[3]);
    *(uint4*)((char*)&g_wblob[mat][1][0] + o) = make_uint4(lo[0], lo[1], lo[2], lo[3]);
}

// ============================ mma.sync fused multi-source GEMM ============================
// C[M,128] = relu(alpha * sum_s A_s[M,128] @ W_s[128,128]^T + bias)
// split-bf16: A*W ~= Ahi*Whi + Ahi*Wlo + Alo*Whi, fp32 accumulate
struct GSrc {
    const float* A;
    const __nv_bfloat16* whi;       // tile-image blobs, 32KB each
    const __nv_bfloat16* wlo;
};

#define SM_AHI 0
#define SM_ALO 32768
#define SM_WHI 65536
#define SM_WLO 98304
#define SM_TOTAL 131072

template <int NS>
__global__ void __launch_bounds__(256, 1) gemm_mma(GSrc s0, GSrc s1, GSrc s2,
                                                   const float* __restrict__ bias,
                                                   float alpha, float* __restrict__ C, int M) {
    extern __shared__ __align__(128) char smem[];
    uint32_t sbase = smem_u32(smem);
    const int tid = threadIdx.x;
    const int wid = tid >> 5;
    const int lane = tid & 31;
    const int warp_m = wid & 1;    // 2 x 64 rows
    const int warp_n = wid >> 1;   // 4 x 32 cols
    const int m0 = blockIdx.x * 128;
    GSrc srcs[3] = {s0, s1, s2};

    float acc[4][4][4];
#pragma unroll
    for (int i = 0; i < 4; i++)
#pragma unroll
        for (int j = 0; j < 4; j++)
#pragma unroll
            for (int k = 0; k < 4; k++) acc[i][j][k] = 0.0f;

    const int a_row = warp_m * 64 + (lane & 15);
    const int a_cbase = (lane >> 4);
    const int w_row = warp_n * 32 + (lane & 7) + ((lane >> 4) << 3);
    const int w_cbase = (lane >> 3) & 1;
    const int l7 = lane & 7;

#pragma unroll
    for (int si = 0; si < NS; si++) {
        __syncthreads();
        // ---- copy W blobs (already tile-image layout) ----
        {
            const uint4* wh = (const uint4*)srcs[si].whi;
            const uint4* wl = (const uint4*)srcs[si].wlo;
            uint4* dh = (uint4*)(smem + SM_WHI);
            uint4* dl = (uint4*)(smem + SM_WLO);
#pragma unroll
            for (int i = tid; i < 2048; i += 256) { dh[i] = wh[i]; dl[i] = wl[i]; }
        }
        // ---- convert A tile fp32 -> bf16 hi/lo into swizzled SMEM ----
        {
            const float* A = srcs[si].A;
#pragma unroll
            for (int ci = tid; ci < 2048; ci += 256) {
                int row = ci >> 4, ch = ci & 15;
                int m = m0 + row;
                float4 v0 = make_float4(0.f, 0.f, 0.f, 0.f), v1 = v0;
                if (m < M) {
                    const float4* g = (const float4*)(A + (size_t)m * F + ch * 8);
                    v0 = g[0]; v1 = g[1];
                }
                float vals[8] = {v0.x, v0.y, v0.z, v0.w, v1.x, v1.y, v1.z, v1.w};
                uint32_t hi[4], lo[4];
#pragma unroll
                for (int j = 0; j < 4; j++) {
                    __nv_bfloat16 h0 = __float2bfloat16_rn(vals[2 * j]);
                    __nv_bfloat16 h1 = __float2bfloat16_rn(vals[2 * j + 1]);
                    __nv_bfloat16 l0 = __float2bfloat16_rn(vals[2 * j] - __bfloat162float(h0));
                    __nv_bfloat16 l1 = __float2bfloat16_rn(vals[2 * j + 1] - __bfloat162float(h1));
                    hi[j] = ((uint32_t)__bfloat16_as_ushort(h1) << 16) | __bfloat16_as_ushort(h0);
                    lo[j] = ((uint32_t)__bfloat16_as_ushort(l1) << 16) | __bfloat16_as_ushort(l0);
                }
                uint32_t o = tile_off(row, ch);
                *(uint4*)(smem + SM_AHI + o) = make_uint4(hi[0], hi[1], hi[2], hi[3]);
                *(uint4*)(smem + SM_ALO + o) = make_uint4(lo[0], lo[1], lo[2], lo[3]);
            }
        }
        __syncthreads();

        // ---- MMA mainloop ----
#pragma unroll
        for (int ks = 0; ks < 8; ks++) {
            uint32_t whi[4][2], wlo[4][2];
#pragma unroll
            for (int p = 0; p < 2; p++) {
                uint32_t woff = (uint32_t)(w_row + p * 16) * 256 +
                                (uint32_t)(((ks * 2 + w_cbase) ^ l7) << 4);
                uint32_t r[4];
                ldm_x4(r, sbase + SM_WHI + woff);
                whi[p * 2][0] = r[0]; whi[p * 2][1] = r[1];
                whi[p * 2 + 1][0] = r[2]; whi[p * 2 + 1][1] = r[3];
                ldm_x4(r, sbase + SM_WLO + woff);
                wlo[p * 2][0] = r[0]; wlo[p * 2][1] = r[1];
                wlo[p * 2 + 1][0] = r[2]; wlo[p * 2 + 1][1] = r[3];
            }
#pragma unroll
            for (int mi = 0; mi < 4; mi++) {
                uint32_t aoff = (uint32_t)(a_row + mi * 16) * 256 +
                                (uint32_t)(((ks * 2 + a_cbase) ^ l7) << 4);
                uint32_t ah[4], al[4];
                ldm_x4(ah, sbase + SM_AHI + aoff);
                ldm_x4(al, sbase + SM_ALO + aoff);
#pragma unroll
                for (int ni = 0; ni < 4; ni++) {
                    mma_bf16(acc[mi][ni], ah, whi[ni]);
                    mma_bf16(acc[mi][ni], ah, wlo[ni]);
                    mma_bf16(acc[mi][ni], al, whi[ni]);
                }
            }
        }
    }

    // ---- epilogue ----
#pragma unroll
    for (int mi = 0; mi < 4; mi++) {
        int m = m0 + warp_m * 64 + mi * 16 + (lane >> 2);
#pragma unroll
        for (int ni = 0; ni < 4; ni++) {
            int n = warp_n * 32 + ni * 8 + (lane & 3) * 2;
            float b0 = __ldg(&bias[n]);
            float b1 = __ldg(&bias[n + 1]);
            if (m < M) {
                float2 o;
                o.x = fmaxf(fmaf(alpha, acc[mi][ni][0], b0), 0.f);
                o.y = fmaxf(fmaf(alpha, acc[mi][ni][1], b1), 0.f);
                *(float2*)(C + (size_t)m * F + n) = o;
            }
            if (m + 8 < M) {
                float2 o;
                o.x = fmaxf(fmaf(alpha, acc[mi][ni][2], b0), 0.f);
                o.y = fmaxf(fmaf(alpha, acc[mi][ni][3], b1), 0.f);
                *(float2*)(C + (size_t)(m + 8) * F + n) = o;
            }
        }
    }
}

// ============================ classifier head ============================
__global__ void __launch_bounds__(256) head_kernel(const float* __restrict__ p2,
                                                   const float* __restrict__ W,
                                                   const float* __restrict__ b,
                                                   float* __restrict__ out, int M) {
    __shared__ float Ws[8 * F];
    int tid = threadIdx.x;
    *(float4*)&Ws[tid * 4] = *(const float4*)(W + tid * 4);
    __syncthreads();
    int gid = blockIdx.x * 256 + tid;
    int m = gid >> 3;
    int c = gid & 7;
    if (m < M) {
        const float4* row = (const float4*)(p2 + (size_t)m * F);
        const float4* w = (const float4*)&Ws[c * F];
        float acc = 0.0f;
#pragma unroll
        for (int k = 0; k < 32; k++) {
            float4 a = row[k];
            float4 ww = w[k];
            acc = fmaf(a.x, ww.x, fmaf(a.y, ww.y, fmaf(a.z, ww.z, fmaf(a.w, ww.w, acc))));
        }
        out[gid] = acc + b[c];
    }
}

// ============================ launch ============================
extern "C" void kernel_launch(void* const* d_in, const int* in_sizes, int n_in,
                              void* d_out, int out_size) {
    const float* x_p    = (const float*)d_in[0];
    const float* x_a    = (const float*)d_in[1];
    const int*   c_src  = (const int*)d_in[2];
    const int*   c_dst  = (const int*)d_in[3];
    const int*   ao_src = (const int*)d_in[4];
    const int*   ao_dst = (const int*)d_in[5];
    const int*   ha_src = (const int*)d_in[6];
    const int*   ha_dst = (const int*)d_in[7];
    const float* l1c_Wl = (const float*)d_in[8];
    const float* l1c_bl = (const float*)d_in[9];
    const float* l1c_Wr = (const float*)d_in[10];
    const float* l1a_Wl = (const float*)d_in[11];
    const float* l1a_bl = (const float*)d_in[12];
    const float* l1a_Wr = (const float*)d_in[13];
    const float* l1h_Wl = (const float*)d_in[14];
    const float* l1h_bl = (const float*)d_in[15];
    const float* l1h_Wr = (const float*)d_in[16];
    const float* l2c_Wl = (const float*)d_in[17];
    const float* l2c_bl = (const float*)d_in[18];
    const float* l2c_Wr = (const float*)d_in[19];
    const float* l2a_Wl = (const float*)d_in[20];
    const float* l2a_bl = (const float*)d_in[21];
    const float* l2a_Wr = (const float*)d_in[22];
    const float* lin_W  = (const float*)d_in[26];
    const float* lin_b  = (const float*)d_in[27];
    float* out = (float*)d_out;

    const int NP = in_sizes[0] / F;
    const int NA = in_sizes[1] / F;
    const int E  = in_sizes[2];
    const int n3 = 2 * NP + NA;

    float *agg_c, *agg_a, *agg_h, *p1, *a1, *p2, *b1, *b2;
    int *cnt3, *cur3, *rp3, *col3, *part;
    __nv_bfloat16* wblob;
    cudaGetSymbolAddress((void**)&agg_c, g_agg_c);
    cudaGetSymbolAddress((void**)&agg_a, g_agg_a);
    cudaGetSymbolAddress((void**)&agg_h, g_agg_h);
    cudaGetSymbolAddress((void**)&p1, g_p1);
    cudaGetSymbolAddress((void**)&a1, g_a1);
    cudaGetSymbolAddress((void**)&p2, g_p2);
    cudaGetSymbolAddress((void**)&b1, g_b1);
    cudaGetSymbolAddress((void**)&b2, g_b2);
    cudaGetSymbolAddress((void**)&wblob, g_wblob);
    cudaGetSymbolAddress((void**)&cnt3, g_cnt3);
    cudaGetSymbolAddress((void**)&cur3, g_cur3);
    cudaGetSymbolAddress((void**)&rp3, g_rp3);
    cudaGetSymbolAddress((void**)&col3, g_col3);
    cudaGetSymbolAddress((void**)&part, g_part);

    cudaFuncSetAttribute(gemm_mma<3>, cudaFuncAttributeMaxDynamicSharedMemorySize, SM_TOTAL);
    cudaFuncSetAttribute(gemm_mma<2>, cudaFuncAttributeMaxDynamicSharedMemorySize, SM_TOTAL);

    const int tb = 256;
    const int eb3 = (3 * E + tb - 1) / tb;
    const int nb3 = (n3 + 2047) / 2048;

    // ---- weight prep ----
    prep_bias_kernel<<<1, 128>>>(l1c_bl, l1a_bl, l2c_bl, l2a_bl);
    W8 w8;
    w8.a[0] = l1c_Wl; w8.b[0] = nullptr;
    w8.a[1] = l1a_Wl; w8.b[1] = nullptr;
    w8.a[2] = l1c_Wr; w8.b[2] = l1a_Wr;    // Wr1 = sum
    w8.a[3] = l1h_Wl; w8.b[3] = nullptr;
    w8.a[4] = l1h_Wr; w8.b[4] = nullptr;
    w8.a[5] = l2c_Wl; w8.b[5] = nullptr;
    w8.a[6] = l2a_Wl; w8.b[6] = nullptr;
    w8.a[7] = l2c_Wr; w8.b[7] = l2a_Wr;    // Wr2 = sum
    prep_w_kernel<<<dim3(8, 8), 256>>>(w8);

    // ---- fused CSR build (all 3 relations, one scan) ----
    cudaMemsetAsync(cnt3, 0, (size_t)n3 * sizeof(int), 0);
    cudaMemsetAsync(cur3, 0, (size_t)n3 * sizeof(int), 0);
    count3_kernel<<<eb3, tb>>>(c_dst, ao_dst, ha_dst, cnt3, E, NP);
    scanA_kernel<<<nb3, 1024>>>(cnt3, part, n3);
    scanB_kernel<<<1, 128>>>(part, rp3 + n3, nb3);
    scanC_kernel<<<nb3, 1024>>>(cnt3, part, rp3, n3);
    fill3_kernel<<<eb3, tb>>>(c_src, c_dst, ao_src, ao_dst, ha_src, ha_dst,
                              rp3, cur3, col3, E, NP);

    const int gb_p = (NP * 32 + tb - 1) / tb;   // warp per node
    const int gb_a = (NA * 32 + tb - 1) / tb;

    // ---- layer 1 mean-gathers (rp segment base = pointer offset) ----
    gather_kernel<<<gb_p, tb>>>(x_p, rp3, col3, agg_c, NP);
    gather_kernel<<<gb_p, tb>>>(x_a, rp3 + NP, col3, agg_a, NP);
    gather_kernel<<<gb_a, tb>>>(x_p, rp3 + 2 * NP, col3, agg_h, NA);

    auto WB = [&](int m, int half) -> const __nv_bfloat16* {
        return wblob + ((size_t)m * 2 + half) * F * F;
    };

    // ---- layer 1 GEMMs ----
    {
        GSrc sc{agg_c, WB(0, 0), WB(0, 1)};
        GSrc sa{agg_a, WB(1, 0), WB(1, 1)};
        GSrc sx{x_p, WB(2, 0), WB(2, 1)};
        gemm_mma<3><<<(NP + 127) / 128, 256, SM_TOTAL>>>(sc, sa, sx, b1, 0.5f, p1, NP);
    }
    {
        GSrc sh{agg_h, WB(3, 0), WB(3, 1)};
        GSrc sxa{x_a, WB(4, 0), WB(4, 1)};
        gemm_mma<2><<<(NA + 127) / 128, 256, SM_TOTAL>>>(sh, sxa, sxa, l1h_bl, 1.0f, a1, NA);
    }

    // ---- layer 2 mean-gathers (reuse CSR) ----
    gather_kernel<<<gb_p, tb>>>(p1, rp3, col3, agg_c, NP);
    gather_kernel<<<gb_p, tb>>>(a1, rp3 + NP, col3, agg_a, NP);

    // ---- layer 2 GEMM ----
    {
        GSrc sc2{agg_c, WB(5, 0), WB(5, 1)};
        GSrc sa2{agg_a, WB(6, 0), WB(6, 1)};
        GSrc sp{p1, WB(7, 0), WB(7, 1)};
        gemm_mma<3><<<(NP + 127) / 128, 256, SM_TOTAL>>>(sc2, sa2, sp, b2, 0.5f, p2, NP);
    }

    // ---- classifier head ----
    head_kernel<<<(NP * 8 + tb - 1) / tb, tb>>>(p2, lin_W, lin_b, out, NP);
}

// round 7
// speedup vs baseline: 2.1538x; 1.0226x over previous
#include <cuda_runtime.h>
#include <cuda_bf16.h>
#include <cstdint>
#include <cstddef>

#define F 128
#define NPMAX 50000
#define NAMAX 100000
#define EMAX 800000
#define N3MAX (2 * NPMAX + NAMAX)

// ============================ helpers ============================
__device__ __forceinline__ uint32_t smem_u32(const void* p) {
    uint32_t a;
    asm("{ .reg .u64 t; cvta.to.shared.u64 t, %1; cvt.u32.u64 %0, t; }" : "=r"(a) : "l"(p));
    return a;
}
__device__ __forceinline__ void ldm_x4(uint32_t* r, uint32_t addr) {
    asm volatile("ldmatrix.sync.aligned.m8n8.x4.shared.b16 {%0,%1,%2,%3}, [%4];"
                 : "=r"(r[0]), "=r"(r[1]), "=r"(r[2]), "=r"(r[3]) : "r"(addr));
}
__device__ __forceinline__ void mma_bf16(float* c, const uint32_t* a, const uint32_t* b) {
    asm volatile(
        "mma.sync.aligned.m16n8k16.row.col.f32.bf16.bf16.f32 "
        "{%0,%1,%2,%3}, {%4,%5,%6,%7}, {%8,%9}, {%0,%1,%2,%3};"
        : "+f"(c[0]), "+f"(c[1]), "+f"(c[2]), "+f"(c[3])
        : "r"(a[0]), "r"(a[1]), "r"(a[2]), "r"(a[3]), "r"(b[0]), "r"(b[1]));
}

// [rows x 128 bf16] tile, 256B/row, 16B chunks, XOR swizzle chunk^(row&7)
__device__ __forceinline__ uint32_t tile_off(int row, int ch) {
    return (uint32_t)(row * 256 + ((ch ^ (row & 7)) << 4));
}

// ============================ device scratch ============================
__device__ float g_agg_c[(size_t)NPMAX * F];
__device__ float g_agg_a[(size_t)NPMAX * F];
__device__ float g_agg_h[(size_t)NAMAX * F];
__device__ float g_p1[(size_t)NPMAX * F];
__device__ float g_a1[(size_t)NAMAX * F];
__device__ float g_p2[(size_t)NPMAX * F];
__device__ float g_b1[F];
__device__ float g_b2[F];
__device__ __nv_bfloat16 g_wblob[8][2][F * F];  // [matrix][hi/lo][tile-image layout]
// fused CSR over 3 relations: segments [0,NP) c | [NP,2NP) a | [2NP,2NP+NA) h
__device__ int g_cnt3[N3MAX];
__device__ int g_cur3[N3MAX];
__device__ int g_rp3[N3MAX + 1];
__device__ int g_col3[3 * EMAX];
__device__ int g_part[128];

// ============================ fused CSR build ============================
__global__ void count3_kernel(const int* __restrict__ cd, const int* __restrict__ ad,
                              const int* __restrict__ hd, int* __restrict__ cnt3,
                              int E, int NP) {
    int i = blockIdx.x * blockDim.x + threadIdx.x;
    if (i < E) atomicAdd(&cnt3[cd[i]], 1);
    else if (i < 2 * E) atomicAdd(&cnt3[NP + ad[i - E]], 1);
    else if (i < 3 * E) atomicAdd(&cnt3[2 * NP + hd[i - 2 * E]], 1);
}

__global__ void __launch_bounds__(1024) scanA_kernel(const int* __restrict__ cnt,
                                                     int* __restrict__ part, int n) {
    __shared__ int wsum[32];
    int tid = threadIdx.x;
    int base = blockIdx.x * 2048 + tid * 2;
    int v = 0;
    if (base < n) v += cnt[base];
    if (base + 1 < n) v += cnt[base + 1];
#pragma unroll
    for (int o = 16; o; o >>= 1) v += __shfl_down_sync(0xFFFFFFFF, v, o);
    if ((tid & 31) == 0) wsum[tid >> 5] = v;
    __syncthreads();
    if (tid < 32) {
        int x = wsum[tid];
#pragma unroll
        for (int o = 16; o; o >>= 1) x += __shfl_down_sync(0xFFFFFFFF, x, o);
        if (tid == 0) part[blockIdx.x] = x;
    }
}

__global__ void scanB_kernel(int* __restrict__ part, int* __restrict__ rp_end, int nb) {
    __shared__ int ws[4];
    int tid = threadIdx.x;     // 128 threads
    int lane = tid & 31, w = tid >> 5;
    int v = (tid < nb) ? part[tid] : 0;
    int x = v;
#pragma unroll
    for (int o = 1; o < 32; o <<= 1) {
        int y = __shfl_up_sync(0xFFFFFFFF, x, o);
        if (lane >= o) x += y;
    }
    if (lane == 31) ws[w] = x;
    __syncthreads();
    int add = 0;
#pragma unroll
    for (int i = 0; i < 4; i++) add += (i < w) ? ws[i] : 0;
    x += add;
    if (tid < nb) part[tid] = x - v;   // exclusive block offset
    if (tid == 127) *rp_end = x;       // grand total
}

__global__ void __launch_bounds__(1024) scanC_kernel(const int* __restrict__ cnt,
                                                     const int* __restrict__ part,
                                                     int* __restrict__ rp, int n) {
    __shared__ int woff[32];
    int tid = threadIdx.x;
    int lane = tid & 31, w = tid >> 5;
    int base = blockIdx.x * 2048 + tid * 2;
    int e0 = (base < n) ? cnt[base] : 0;
    int e1 = (base + 1 < n) ? cnt[base + 1] : 0;
    int p = e0 + e1;
    int x = p;
#pragma unroll
    for (int o = 1; o < 32; o <<= 1) {
        int y = __shfl_up_sync(0xFFFFFFFF, x, o);
        if (lane >= o) x += y;
    }
    if (lane == 31) woff[w] = x;
    __syncthreads();
    if (tid < 32) {
        int y = woff[tid];
        int z = y;
#pragma unroll
        for (int o = 1; o < 32; o <<= 1) {
            int t = __shfl_up_sync(0xFFFFFFFF, z, o);
            if (tid >= o) z += t;
        }
        woff[tid] = z - y;
    }
    __syncthreads();
    int off = part[blockIdx.x] + woff[w] + x - p;
    if (base < n) rp[base] = off;
    if (base + 1 < n) rp[base + 1] = off + e0;
}

__global__ void fill3_kernel(const int* __restrict__ cs, const int* __restrict__ cd,
                             const int* __restrict__ as, const int* __restrict__ ad,
                             const int* __restrict__ hs, const int* __restrict__ hd,
                             const int* __restrict__ rp3, int* __restrict__ cur3,
                             int* __restrict__ col3, int E, int NP) {
    int i = blockIdx.x * blockDim.x + threadIdx.x;
    int s, d;
    if (i < E) { s = cs[i]; d = cd[i]; }
    else if (i < 2 * E) { s = as[i - E]; d = NP + ad[i - E]; }
    else if (i < 3 * E) { s = hs[i - 2 * E]; d = 2 * NP + hd[i - 2 * E]; }
    else return;
    int p = atomicAdd(&cur3[d], 1);
    col3[rp3[d] + p] = s;
}

// ============================ CSR mean-gather: warp per dst node, unroll-2 ============================
__global__ void __launch_bounds__(256) gather_kernel(const float* __restrict__ x,
                                                     const int* __restrict__ rp,
                                                     const int* __restrict__ col,
                                                     float* __restrict__ out, int n) {
    int w = (blockIdx.x * blockDim.x + threadIdx.x) >> 5;
    int lane = threadIdx.x & 31;
    if (w >= n) return;
    int s = __ldg(&rp[w]);
    int e = __ldg(&rp[w + 1]);
    float4 acc0 = make_float4(0.f, 0.f, 0.f, 0.f);
    float4 acc1 = make_float4(0.f, 0.f, 0.f, 0.f);
    int i = s;
    for (; i + 2 <= e; i += 2) {
        int c0 = __ldg(&col[i]);
        int c1 = __ldg(&col[i + 1]);
        float4 v0 = *(const float4*)(x + (size_t)c0 * F + lane * 4);
        float4 v1 = *(const float4*)(x + (size_t)c1 * F + lane * 4);
        acc0.x += v0.x; acc0.y += v0.y; acc0.z += v0.z; acc0.w += v0.w;
        acc1.x += v1.x; acc1.y += v1.y; acc1.z += v1.z; acc1.w += v1.w;
    }
    if (i < e) {
        int c = __ldg(&col[i]);
        float4 v = *(const float4*)(x + (size_t)c * F + lane * 4);
        acc0.x += v.x; acc0.y += v.y; acc0.z += v.z; acc0.w += v.w;
    }
    float sc = 1.0f / fmaxf((float)(e - s), 1.0f);
    *(float4*)(out + (size_t)w * F + lane * 4) =
        make_float4((acc0.x + acc1.x) * sc, (acc0.y + acc1.y) * sc,
                    (acc0.z + acc1.z) * sc, (acc0.w + acc1.w) * sc);
}

// ============================ small kernels ============================
__global__ void prep_bias_kernel(const float* __restrict__ b1c, const float* __restrict__ b1a,
                                 const float* __restrict__ b2c, const float* __restrict__ b2a) {
    int i = threadIdx.x;
    if (i < F) {
        g_b1[i] = 0.5f * (b1c[i] + b1a[i]);
        g_b2[i] = 0.5f * (b2c[i] + b2a[i]);
    }
}

struct W8 { const float* a[8]; const float* b[8]; };

__global__ void prep_w_kernel(W8 w) {
    int mat = blockIdx.y;
    int ci = blockIdx.x * 256 + threadIdx.x;   // 0..2047, chunk of 8 elems
    if (ci >= 2048) return;
    int row = ci >> 4, ch = ci & 15;
    const float* pa = w.a[mat];
    const float* pb = w.b[mat];
    int base = row * F + ch * 8;
    uint32_t hi[4], lo[4];
#pragma unroll
    for (int j = 0; j < 4; j++) {
        float x0 = pa[base + 2 * j], x1 = pa[base + 2 * j + 1];
        if (pb) { x0 += pb[base + 2 * j]; x1 += pb[base + 2 * j + 1]; }
        __nv_bfloat16 h0 = __float2bfloat16_rn(x0);
        __nv_bfloat16 h1 = __float2bfloat16_rn(x1);
        __nv_bfloat16 l0 = __float2bfloat16_rn(x0 - __bfloat162float(h0));
        __nv_bfloat16 l1 = __float2bfloat16_rn(x1 - __bfloat162float(h1));
        hi[j] = ((uint32_t)__bfloat16_as_ushort(h1) << 16) | __bfloat16_as_ushort(h0);
        lo[j] = ((uint32_t)__bfloat16_as_ushort(l1) << 16) | __bfloat16_as_ushort(l0);
    }
    uint32_t o = tile_off(row, ch);
    *(uint4*)((char*)&g_wblob[mat][0][0] + o) = make_uint4(hi[0], hi[1], hi[2], hi[3]);
    *(uint4*)((char*)&g_wblob[mat][1][0] + o) = make_uint4(lo[0], lo[1], lo[2], lo[3]);
}

// ============================ mma.sync fused multi-source GEMM (M-tile 64, 2 CTA/SM) ============================
// C[M,128] = relu(alpha * sum_s A_s[M,128] @ W_s[128,128]^T + bias)
// split-bf16: A*W ~= Ahi*Whi + Ahi*Wlo + Alo*Whi, fp32 accumulate
struct GSrc {
    const float* A;
    const __nv_bfloat16* whi;       // tile-image blobs, 32KB each
    const __nv_bfloat16* wlo;
};

#define SM_AHI 0
#define SM_ALO 16384
#define SM_WHI 32768
#define SM_WLO 65536
#define SM_TOTAL 98304

template <int NS>
__global__ void __launch_bounds__(256) gemm_mma(GSrc s0, GSrc s1, GSrc s2,
                                                const float* __restrict__ bias,
                                                float alpha, float* __restrict__ C, int M) {
    extern __shared__ __align__(128) char smem[];
    uint32_t sbase = smem_u32(smem);
    const int tid = threadIdx.x;
    const int wid = tid >> 5;
    const int lane = tid & 31;
    const int warp_m = wid & 1;    // 2 x 32 rows
    const int warp_n = wid >> 1;   // 4 x 32 cols
    const int m0 = blockIdx.x * 64;
    GSrc srcs[3] = {s0, s1, s2};

    float acc[2][4][4];
#pragma unroll
    for (int i = 0; i < 2; i++)
#pragma unroll
        for (int j = 0; j < 4; j++)
#pragma unroll
            for (int k = 0; k < 4; k++) acc[i][j][k] = 0.0f;

    const int a_row = warp_m * 32 + (lane & 15);
    const int a_cbase = (lane >> 4);
    const int w_row = warp_n * 32 + (lane & 7) + ((lane >> 4) << 3);
    const int w_cbase = (lane >> 3) & 1;
    const int l7 = lane & 7;

#pragma unroll
    for (int si = 0; si < NS; si++) {
        __syncthreads();
        // ---- copy W blobs (already tile-image layout) ----
        {
            const uint4* wh = (const uint4*)srcs[si].whi;
            const uint4* wl = (const uint4*)srcs[si].wlo;
            uint4* dh = (uint4*)(smem + SM_WHI);
            uint4* dl = (uint4*)(smem + SM_WLO);
#pragma unroll
            for (int i = tid; i < 2048; i += 256) { dh[i] = wh[i]; dl[i] = wl[i]; }
        }
        // ---- convert A tile (64 rows) fp32 -> bf16 hi/lo into swizzled SMEM ----
        {
            const float* A = srcs[si].A;
#pragma unroll
            for (int ci = tid; ci < 1024; ci += 256) {
                int row = ci >> 4, ch = ci & 15;
                int m = m0 + row;
                float4 v0 = make_float4(0.f, 0.f, 0.f, 0.f), v1 = v0;
                if (m < M) {
                    const float4* g = (const float4*)(A + (size_t)m * F + ch * 8);
                    v0 = g[0]; v1 = g[1];
                }
                float vals[8] = {v0.x, v0.y, v0.z, v0.w, v1.x, v1.y, v1.z, v1.w};
                uint32_t hi[4], lo[4];
#pragma unroll
                for (int j = 0; j < 4; j++) {
                    __nv_bfloat16 h0 = __float2bfloat16_rn(vals[2 * j]);
                    __nv_bfloat16 h1 = __float2bfloat16_rn(vals[2 * j + 1]);
                    __nv_bfloat16 l0 = __float2bfloat16_rn(vals[2 * j] - __bfloat162float(h0));
                    __nv_bfloat16 l1 = __float2bfloat16_rn(vals[2 * j + 1] - __bfloat162float(h1));
                    hi[j] = ((uint32_t)__bfloat16_as_ushort(h1) << 16) | __bfloat16_as_ushort(h0);
                    lo[j] = ((uint32_t)__bfloat16_as_ushort(l1) << 16) | __bfloat16_as_ushort(l0);
                }
                uint32_t o = tile_off(row, ch);
                *(uint4*)(smem + SM_AHI + o) = make_uint4(hi[0], hi[1], hi[2], hi[3]);
                *(uint4*)(smem + SM_ALO + o) = make_uint4(lo[0], lo[1], lo[2], lo[3]);
            }
        }
        __syncthreads();

        // ---- MMA mainloop ----
#pragma unroll
        for (int ks = 0; ks < 8; ks++) {
            uint32_t whi[4][2], wlo[4][2];
#pragma unroll
            for (int p = 0; p < 2; p++) {
                uint32_t woff = (uint32_t)(w_row + p * 16) * 256 +
                                (uint32_t)(((ks * 2 + w_cbase) ^ l7) << 4);
                uint32_t r[4];
                ldm_x4(r, sbase + SM_WHI + woff);
                whi[p * 2][0] = r[0]; whi[p * 2][1] = r[1];
                whi[p * 2 + 1][0] = r[2]; whi[p * 2 + 1][1] = r[3];
                ldm_x4(r, sbase + SM_WLO + woff);
                wlo[p * 2][0] = r[0]; wlo[p * 2][1] = r[1];
                wlo[p * 2 + 1][0] = r[2]; wlo[p * 2 + 1][1] = r[3];
            }
#pragma unroll
            for (int mi = 0; mi < 2; mi++) {
                uint32_t aoff = (uint32_t)(a_row + mi * 16) * 256 +
                                (uint32_t)(((ks * 2 + a_cbase) ^ l7) << 4);
                uint32_t ah[4], al[4];
                ldm_x4(ah, sbase + SM_AHI + aoff);
                ldm_x4(al, sbase + SM_ALO + aoff);
#pragma unroll
                for (int ni = 0; ni < 4; ni++) {
                    mma_bf16(acc[mi][ni], ah, whi[ni]);
                    mma_bf16(acc[mi][ni], ah, wlo[ni]);
                    mma_bf16(acc[mi][ni], al, whi[ni]);
                }
            }
        }
    }

    // ---- epilogue ----
#pragma unroll
    for (int mi = 0; mi < 2; mi++) {
        int m = m0 + warp_m * 32 + mi * 16 + (lane >> 2);
#pragma unroll
        for (int ni = 0; ni < 4; ni++) {
            int n = warp_n * 32 + ni * 8 + (lane & 3) * 2;
            float b0 = __ldg(&bias[n]);
            float b1 = __ldg(&bias[n + 1]);
            if (m < M) {
                float2 o;
                o.x = fmaxf(fmaf(alpha, acc[mi][ni][0], b0), 0.f);
                o.y = fmaxf(fmaf(alpha, acc[mi][ni][1], b1), 0.f);
                *(float2*)(C + (size_t)m * F + n) = o;
            }
            if (m + 8 < M) {
                float2 o;
                o.x = fmaxf(fmaf(alpha, acc[mi][ni][2], b0), 0.f);
                o.y = fmaxf(fmaf(alpha, acc[mi][ni][3], b1), 0.f);
                *(float2*)(C + (size_t)(m + 8) * F + n) = o;
            }
        }
    }
}

// ============================ classifier head ============================
__global__ void __launch_bounds__(256) head_kernel(const float* __restrict__ p2,
                                                   const float* __restrict__ W,
                                                   const float* __restrict__ b,
                                                   float* __restrict__ out, int M) {
    __shared__ float Ws[8 * F];
    int tid = threadIdx.x;
    *(float4*)&Ws[tid * 4] = *(const float4*)(W + tid * 4);
    __syncthreads();
    int gid = blockIdx.x * 256 + tid;
    int m = gid >> 3;
    int c = gid & 7;
    if (m < M) {
        const float4* row = (const float4*)(p2 + (size_t)m * F);
        const float4* w = (const float4*)&Ws[c * F];
        float acc = 0.0f;
#pragma unroll
        for (int k = 0; k < 32; k++) {
            float4 a = row[k];
            float4 ww = w[k];
            acc = fmaf(a.x, ww.x, fmaf(a.y, ww.y, fmaf(a.z, ww.z, fmaf(a.w, ww.w, acc))));
        }
        out[gid] = acc + b[c];
    }
}

// ============================ launch ============================
extern "C" void kernel_launch(void* const* d_in, const int* in_sizes, int n_in,
                              void* d_out, int out_size) {
    const float* x_p    = (const float*)d_in[0];
    const float* x_a    = (const float*)d_in[1];
    const int*   c_src  = (const int*)d_in[2];
    const int*   c_dst  = (const int*)d_in[3];
    const int*   ao_src = (const int*)d_in[4];
    const int*   ao_dst = (const int*)d_in[5];
    const int*   ha_src = (const int*)d_in[6];
    const int*   ha_dst = (const int*)d_in[7];
    const float* l1c_Wl = (const float*)d_in[8];
    const float* l1c_bl = (const float*)d_in[9];
    const float* l1c_Wr = (const float*)d_in[10];
    const float* l1a_Wl = (const float*)d_in[11];
    const float* l1a_bl = (const float*)d_in[12];
    const float* l1a_Wr = (const float*)d_in[13];
    const float* l1h_Wl = (const float*)d_in[14];
    const float* l1h_bl = (const float*)d_in[15];
    const float* l1h_Wr = (const float*)d_in[16];
    const float* l2c_Wl = (const float*)d_in[17];
    const float* l2c_bl = (const float*)d_in[18];
    const float* l2c_Wr = (const float*)d_in[19];
    const float* l2a_Wl = (const float*)d_in[20];
    const float* l2a_bl = (const float*)d_in[21];
    const float* l2a_Wr = (const float*)d_in[22];
    const float* lin_W  = (const float*)d_in[26];
    const float* lin_b  = (const float*)d_in[27];
    float* out = (float*)d_out;

    const int NP = in_sizes[0] / F;
    const int NA = in_sizes[1] / F;
    const int E  = in_sizes[2];
    const int n3 = 2 * NP + NA;

    float *agg_c, *agg_a, *agg_h, *p1, *a1, *p2, *b1, *b2;
    int *cnt3, *cur3, *rp3, *col3, *part;
    __nv_bfloat16* wblob;
    cudaGetSymbolAddress((void**)&agg_c, g_agg_c);
    cudaGetSymbolAddress((void**)&agg_a, g_agg_a);
    cudaGetSymbolAddress((void**)&agg_h, g_agg_h);
    cudaGetSymbolAddress((void**)&p1, g_p1);
    cudaGetSymbolAddress((void**)&a1, g_a1);
    cudaGetSymbolAddress((void**)&p2, g_p2);
    cudaGetSymbolAddress((void**)&b1, g_b1);
    cudaGetSymbolAddress((void**)&b2, g_b2);
    cudaGetSymbolAddress((void**)&wblob, g_wblob);
    cudaGetSymbolAddress((void**)&cnt3, g_cnt3);
    cudaGetSymbolAddress((void**)&cur3, g_cur3);
    cudaGetSymbolAddress((void**)&rp3, g_rp3);
    cudaGetSymbolAddress((void**)&col3, g_col3);
    cudaGetSymbolAddress((void**)&part, g_part);

    cudaFuncSetAttribute(gemm_mma<3>, cudaFuncAttributeMaxDynamicSharedMemorySize, SM_TOTAL);
    cudaFuncSetAttribute(gemm_mma<2>, cudaFuncAttributeMaxDynamicSharedMemorySize, SM_TOTAL);

    const int tb = 256;
    const int eb3 = (3 * E + tb - 1) / tb;
    const int nb3 = (n3 + 2047) / 2048;

    // ---- fused CSR build (all 3 relations, one scan) ----
    cudaMemsetAsync(cnt3, 0, (size_t)n3 * sizeof(int), 0);
    cudaMemsetAsync(cur3, 0, (size_t)n3 * sizeof(int), 0);
    count3_kernel<<<eb3, tb>>>(c_dst, ao_dst, ha_dst, cnt3, E, NP);
    scanA_kernel<<<nb3, 1024>>>(cnt3, part, n3);
    scanB_kernel<<<1, 128>>>(part, rp3 + n3, nb3);
    scanC_kernel<<<nb3, 1024>>>(cnt3, part, rp3, n3);
    fill3_kernel<<<eb3, tb>>>(c_src, c_dst, ao_src, ao_dst, ha_src, ha_dst,
                              rp3, cur3, col3, E, NP);

    const int gb_p = (NP * 32 + tb - 1) / tb;   // warp per node
    const int gb_a = (NA * 32 + tb - 1) / tb;

    // ---- layer 1 mean-gathers (rp segment base = pointer offset) ----
    gather_kernel<<<gb_p, tb>>>(x_p, rp3, col3, agg_c, NP);
    gather_kernel<<<gb_p, tb>>>(x_a, rp3 + NP, col3, agg_a, NP);
    gather_kernel<<<gb_a, tb>>>(x_p, rp3 + 2 * NP, col3, agg_h, NA);

    // ---- weight prep (only needed before GEMMs; placed here so ncu -s 5 lands on gather) ----
    prep_bias_kernel<<<1, 128>>>(l1c_bl, l1a_bl, l2c_bl, l2a_bl);
    W8 w8;
    w8.a[0] = l1c_Wl; w8.b[0] = nullptr;
    w8.a[1] = l1a_Wl; w8.b[1] = nullptr;
    w8.a[2] = l1c_Wr; w8.b[2] = l1a_Wr;    // Wr1 = sum
    w8.a[3] = l1h_Wl; w8.b[3] = nullptr;
    w8.a[4] = l1h_Wr; w8.b[4] = nullptr;
    w8.a[5] = l2c_Wl; w8.b[5] = nullptr;
    w8.a[6] = l2a_Wl; w8.b[6] = nullptr;
    w8.a[7] = l2c_Wr; w8.b[7] = l2a_Wr;    // Wr2 = sum
    prep_w_kernel<<<dim3(8, 8), 256>>>(w8);

    auto WB = [&](int m, int half) -> const __nv_bfloat16* {
        return wblob + ((size_t)m * 2 + half) * F * F;
    };

    // ---- layer 1 GEMMs (M-tile 64, 2 CTA/SM) ----
    {
        GSrc sc{agg_c, WB(0, 0), WB(0, 1)};
        GSrc sa{agg_a, WB(1, 0), WB(1, 1)};
        GSrc sx{x_p, WB(2, 0), WB(2, 1)};
        gemm_mma<3><<<(NP + 63) / 64, 256, SM_TOTAL>>>(sc, sa, sx, b1, 0.5f, p1, NP);
    }
    {
        GSrc sh{agg_h, WB(3, 0), WB(3, 1)};
        GSrc sxa{x_a, WB(4, 0), WB(4, 1)};
        gemm_mma<2><<<(NA + 63) / 64, 256, SM_TOTAL>>>(sh, sxa, sxa, l1h_bl, 1.0f, a1, NA);
    }

    // ---- layer 2 mean-gathers (reuse CSR) ----
    gather_kernel<<<gb_p, tb>>>(p1, rp3, col3, agg_c, NP);
    gather_kernel<<<gb_p, tb>>>(a1, rp3 + NP, col3, agg_a, NP);

    // ---- layer 2 GEMM ----
    {
        GSrc sc2{agg_c, WB(5, 0), WB(5, 1)};
        GSrc sa2{agg_a, WB(6, 0), WB(6, 1)};
        GSrc sp{p1, WB(7, 0), WB(7, 1)};
        gemm_mma<3><<<(NP + 63) / 64, 256, SM_TOTAL>>>(sc2, sa2, sp, b2, 0.5f, p2, NP);
    }

    // ---- classifier head ----
    head_kernel<<<(NP * 8 + tb - 1) / tb, tb>>>(p2, lin_W, lin_b, out, NP);
}

// round 8
// speedup vs baseline: 2.3685x; 1.0997x over previous
#include <cuda_runtime.h>
#include <cuda_bf16.h>
#include <cstdint>
#include <cstddef>

#define F 128
#define NPMAX 50000
#define NAMAX 100000
#define EMAX 800000
#define N3MAX (2 * NPMAX + NAMAX)

// ============================ helpers ============================
__device__ __forceinline__ uint32_t smem_u32(const void* p) {
    uint32_t a;
    asm("{ .reg .u64 t; cvta.to.shared.u64 t, %1; cvt.u32.u64 %0, t; }" : "=r"(a) : "l"(p));
    return a;
}
__device__ __forceinline__ void ldm_x4(uint32_t* r, uint32_t addr) {
    asm volatile("ldmatrix.sync.aligned.m8n8.x4.shared.b16 {%0,%1,%2,%3}, [%4];"
                 : "=r"(r[0]), "=r"(r[1]), "=r"(r[2]), "=r"(r[3]) : "r"(addr));
}
__device__ __forceinline__ void mma_bf16(float* c, const uint32_t* a, const uint32_t* b) {
    asm volatile(
        "mma.sync.aligned.m16n8k16.row.col.f32.bf16.bf16.f32 "
        "{%0,%1,%2,%3}, {%4,%5,%6,%7}, {%8,%9}, {%0,%1,%2,%3};"
        : "+f"(c[0]), "+f"(c[1]), "+f"(c[2]), "+f"(c[3])
        : "r"(a[0]), "r"(a[1]), "r"(a[2]), "r"(a[3]), "r"(b[0]), "r"(b[1]));
}

// [rows x 128 bf16] tile, 256B/row, 16B chunks, XOR swizzle chunk^(row&7)
__device__ __forceinline__ uint32_t tile_off(int row, int ch) {
    return (uint32_t)(row * 256 + ((ch ^ (row & 7)) << 4));
}

// ============================ device scratch ============================
__device__ float g_agg_c[(size_t)NPMAX * F];
__device__ float g_agg_a[(size_t)NPMAX * F];
__device__ float g_agg_h[(size_t)NAMAX * F];
__device__ float g_agg_c2[(size_t)NPMAX * F];   // layer-2 (separate: overlap WAR safety)
__device__ float g_agg_a2[(size_t)NPMAX * F];
__device__ float g_p1[(size_t)NPMAX * F];
__device__ float g_a1[(size_t)NAMAX * F];
__device__ float g_p2[(size_t)NPMAX * F];
__device__ float g_b1[F];
__device__ float g_b2[F];
__device__ __nv_bfloat16 g_wblob[8][2][F * F];  // [matrix][hi/lo][tile-image layout]
// fused CSR over 3 relations: segments [0,NP) c | [NP,2NP) a | [2NP,2NP+NA) h
__device__ int g_cnt3[N3MAX];
__device__ int g_rp3[N3MAX + 1];
__device__ int g_col3[3 * EMAX];
__device__ int g_part[128];

// ============================ fused CSR build ============================
__global__ void count3_kernel(const int* __restrict__ cd, const int* __restrict__ ad,
                              const int* __restrict__ hd, int* __restrict__ cnt3,
                              int E, int NP) {
    int i = blockIdx.x * blockDim.x + threadIdx.x;
    if (i < E) atomicAdd(&cnt3[cd[i]], 1);
    else if (i < 2 * E) atomicAdd(&cnt3[NP + ad[i - E]], 1);
    else if (i < 3 * E) atomicAdd(&cnt3[2 * NP + hd[i - 2 * E]], 1);
}

__global__ void __launch_bounds__(1024) scanA_kernel(const int* __restrict__ cnt,
                                                     int* __restrict__ part, int n) {
    __shared__ int wsum[32];
    int tid = threadIdx.x;
    int base = blockIdx.x * 2048 + tid * 2;
    int v = 0;
    if (base < n) v += cnt[base];
    if (base + 1 < n) v += cnt[base + 1];
#pragma unroll
    for (int o = 16; o; o >>= 1) v += __shfl_down_sync(0xFFFFFFFF, v, o);
    if ((tid & 31) == 0) wsum[tid >> 5] = v;
    __syncthreads();
    if (tid < 32) {
        int x = wsum[tid];
#pragma unroll
        for (int o = 16; o; o >>= 1) x += __shfl_down_sync(0xFFFFFFFF, x, o);
        if (tid == 0) part[blockIdx.x] = x;
    }
}

__global__ void scanB_kernel(int* __restrict__ part, int* __restrict__ rp_end, int nb) {
    __shared__ int ws[4];
    int tid = threadIdx.x;     // 128 threads
    int lane = tid & 31, w = tid >> 5;
    int v = (tid < nb) ? part[tid] : 0;
    int x = v;
#pragma unroll
    for (int o = 1; o < 32; o <<= 1) {
        int y = __shfl_up_sync(0xFFFFFFFF, x, o);
        if (lane >= o) x += y;
    }
    if (lane == 31) ws[w] = x;
    __syncthreads();
    int add = 0;
#pragma unroll
    for (int i = 0; i < 4; i++) add += (i < w) ? ws[i] : 0;
    x += add;
    if (tid < nb) part[tid] = x - v;   // exclusive block offset
    if (tid == 127) *rp_end = x;       // grand total
}

__global__ void __launch_bounds__(1024) scanC_kernel(const int* __restrict__ cnt,
                                                     const int* __restrict__ part,
                                                     int* __restrict__ rp, int n) {
    __shared__ int woff[32];
    int tid = threadIdx.x;
    int lane = tid & 31, w = tid >> 5;
    int base = blockIdx.x * 2048 + tid * 2;
    int e0 = (base < n) ? cnt[base] : 0;
    int e1 = (base + 1 < n) ? cnt[base + 1] : 0;
    int p = e0 + e1;
    int x = p;
#pragma unroll
    for (int o = 1; o < 32; o <<= 1) {
        int y = __shfl_up_sync(0xFFFFFFFF, x, o);
        if (lane >= o) x += y;
    }
    if (lane == 31) woff[w] = x;
    __syncthreads();
    if (tid < 32) {
        int y = woff[tid];
        int z = y;
#pragma unroll
        for (int o = 1; o < 32; o <<= 1) {
            int t = __shfl_up_sync(0xFFFFFFFF, z, o);
            if (tid >= o) z += t;
        }
        woff[tid] = z - y;
    }
    __syncthreads();
    int off = part[blockIdx.x] + woff[w] + x - p;
    if (base < n) rp[base] = off;
    if (base + 1 < n) rp[base + 1] = off + e0;
}

// uses cnt3 as a countdown cursor (no cur3 buffer/memset); fill order within a segment
// is reversed, which is irrelevant for a sum.
__global__ void fill3_kernel(const int* __restrict__ cs, const int* __restrict__ cd,
                             const int* __restrict__ as, const int* __restrict__ ad,
                             const int* __restrict__ hs, const int* __restrict__ hd,
                             const int* __restrict__ rp3, int* __restrict__ cnt3,
                             int* __restrict__ col3, int E, int NP) {
    int i = blockIdx.x * blockDim.x + threadIdx.x;
    int s, d;
    if (i < E) { s = cs[i]; d = cd[i]; }
    else if (i < 2 * E) { s = as[i - E]; d = NP + ad[i - E]; }
    else if (i < 3 * E) { s = hs[i - 2 * E]; d = 2 * NP + hd[i - 2 * E]; }
    else return;
    int p = atomicSub(&cnt3[d], 1) - 1;
    col3[rp3[d] + p] = s;
}

// ============================ CSR mean-gather: warp per dst node, unroll-2 ============================
__global__ void __launch_bounds__(256) gather_kernel(const float* __restrict__ x,
                                                     const int* __restrict__ rp,
                                                     const int* __restrict__ col,
                                                     float* __restrict__ out, int n) {
    int w = (blockIdx.x * blockDim.x + threadIdx.x) >> 5;
    int lane = threadIdx.x & 31;
    if (w >= n) return;
    int s = __ldg(&rp[w]);
    int e = __ldg(&rp[w + 1]);
    float4 acc0 = make_float4(0.f, 0.f, 0.f, 0.f);
    float4 acc1 = make_float4(0.f, 0.f, 0.f, 0.f);
    int i = s;
    for (; i + 2 <= e; i += 2) {
        int c0 = __ldg(&col[i]);
        int c1 = __ldg(&col[i + 1]);
        float4 v0 = *(const float4*)(x + (size_t)c0 * F + lane * 4);
        float4 v1 = *(const float4*)(x + (size_t)c1 * F + lane * 4);
        acc0.x += v0.x; acc0.y += v0.y; acc0.z += v0.z; acc0.w += v0.w;
        acc1.x += v1.x; acc1.y += v1.y; acc1.z += v1.z; acc1.w += v1.w;
    }
    if (i < e) {
        int c = __ldg(&col[i]);
        float4 v = *(const float4*)(x + (size_t)c * F + lane * 4);
        acc0.x += v.x; acc0.y += v.y; acc0.z += v.z; acc0.w += v.w;
    }
    float sc = 1.0f / fmaxf((float)(e - s), 1.0f);
    *(float4*)(out + (size_t)w * F + lane * 4) =
        make_float4((acc0.x + acc1.x) * sc, (acc0.y + acc1.y) * sc,
                    (acc0.z + acc1.z) * sc, (acc0.w + acc1.w) * sc);
}

// ============================ small kernels ============================
__global__ void prep_bias_kernel(const float* __restrict__ b1c, const float* __restrict__ b1a,
                                 const float* __restrict__ b2c, const float* __restrict__ b2a) {
    int i = threadIdx.x;
    if (i < F) {
        g_b1[i] = 0.5f * (b1c[i] + b1a[i]);
        g_b2[i] = 0.5f * (b2c[i] + b2a[i]);
    }
}

struct W8 { const float* a[8]; const float* b[8]; };

__global__ void prep_w_kernel(W8 w) {
    int mat = blockIdx.y;
    int ci = blockIdx.x * 256 + threadIdx.x;   // 0..2047, chunk of 8 elems
    if (ci >= 2048) return;
    int row = ci >> 4, ch = ci & 15;
    const float* pa = w.a[mat];
    const float* pb = w.b[mat];
    int base = row * F + ch * 8;
    uint32_t hi[4], lo[4];
#pragma unroll
    for (int j = 0; j < 4; j++) {
        float x0 = pa[base + 2 * j], x1 = pa[base + 2 * j + 1];
        if (pb) { x0 += pb[base + 2 * j]; x1 += pb[base + 2 * j + 1]; }
        __nv_bfloat16 h0 = __float2bfloat16_rn(x0);
        __nv_bfloat16 h1 = __float2bfloat16_rn(x1);
        __nv_bfloat16 l0 = __float2bfloat16_rn(x0 - __bfloat162float(h0));
        __nv_bfloat16 l1 = __float2bfloat16_rn(x1 - __bfloat162float(h1));
        hi[j] = ((uint32_t)__bfloat16_as_ushort(h1) << 16) | __bfloat16_as_ushort(h0);
        lo[j] = ((uint32_t)__bfloat16_as_ushort(l1) << 16) | __bfloat16_as_ushort(l0);
    }
    uint32_t o = tile_off(row, ch);
    *(uint4*)((char*)&g_wblob[mat][0][0] + o) = make_uint4(hi[0], hi[1], hi[2], hi[3]);
    *(uint4*)((char*)&g_wblob[mat][1][0] + o) = make_uint4(lo[0], lo[1], lo[2], lo[3]);
}

// ============================ mma.sync fused multi-source GEMM (M-tile 64) ============================
// C[M,128] = relu(alpha * sum_s A_s[M,128] @ W_s[128,128]^T + bias)
// split-bf16: A*W ~= Ahi*Whi + Ahi*Wlo + Alo*Whi, fp32 accumulate
struct GSrc {
    const float* A;
    const __nv_bfloat16* whi;       // tile-image blobs, 32KB each
    const __nv_bfloat16* wlo;
};

#define SM_AHI 0
#define SM_ALO 16384
#define SM_WHI 32768
#define SM_WLO 65536
#define SM_TOTAL 98304

template <int NS>
__global__ void __launch_bounds__(256) gemm_mma(GSrc s0, GSrc s1, GSrc s2,
                                                const float* __restrict__ bias,
                                                float alpha, float* __restrict__ C, int M) {
    extern __shared__ __align__(128) char smem[];
    uint32_t sbase = smem_u32(smem);
    const int tid = threadIdx.x;
    const int wid = tid >> 5;
    const int lane = tid & 31;
    const int warp_m = wid & 1;    // 2 x 32 rows
    const int warp_n = wid >> 1;   // 4 x 32 cols
    const int m0 = blockIdx.x * 64;
    GSrc srcs[3] = {s0, s1, s2};

    float acc[2][4][4];
#pragma unroll
    for (int i = 0; i < 2; i++)
#pragma unroll
        for (int j = 0; j < 4; j++)
#pragma unroll
            for (int k = 0; k < 4; k++) acc[i][j][k] = 0.0f;

    const int a_row = warp_m * 32 + (lane & 15);
    const int a_cbase = (lane >> 4);
    const int w_row = warp_n * 32 + (lane & 7) + ((lane >> 4) << 3);
    const int w_cbase = (lane >> 3) & 1;
    const int l7 = lane & 7;

#pragma unroll
    for (int si = 0; si < NS; si++) {
        __syncthreads();
        {
            const uint4* wh = (const uint4*)srcs[si].whi;
            const uint4* wl = (const uint4*)srcs[si].wlo;
            uint4* dh = (uint4*)(smem + SM_WHI);
            uint4* dl = (uint4*)(smem + SM_WLO);
#pragma unroll
            for (int i = tid; i < 2048; i += 256) { dh[i] = wh[i]; dl[i] = wl[i]; }
        }
        {
            const float* A = srcs[si].A;
#pragma unroll
            for (int ci = tid; ci < 1024; ci += 256) {
                int row = ci >> 4, ch = ci & 15;
                int m = m0 + row;
                float4 v0 = make_float4(0.f, 0.f, 0.f, 0.f), v1 = v0;
                if (m < M) {
                    const float4* g = (const float4*)(A + (size_t)m * F + ch * 8);
                    v0 = g[0]; v1 = g[1];
                }
                float vals[8] = {v0.x, v0.y, v0.z, v0.w, v1.x, v1.y, v1.z, v1.w};
                uint32_t hi[4], lo[4];
#pragma unroll
                for (int j = 0; j < 4; j++) {
                    __nv_bfloat16 h0 = __float2bfloat16_rn(vals[2 * j]);
                    __nv_bfloat16 h1 = __float2bfloat16_rn(vals[2 * j + 1]);
                    __nv_bfloat16 l0 = __float2bfloat16_rn(vals[2 * j] - __bfloat162float(h0));
                    __nv_bfloat16 l1 = __float2bfloat16_rn(vals[2 * j + 1] - __bfloat162float(h1));
                    hi[j] = ((uint32_t)__bfloat16_as_ushort(h1) << 16) | __bfloat16_as_ushort(h0);
                    lo[j] = ((uint32_t)__bfloat16_as_ushort(l1) << 16) | __bfloat16_as_ushort(l0);
                }
                uint32_t o = tile_off(row, ch);
                *(uint4*)(smem + SM_AHI + o) = make_uint4(hi[0], hi[1], hi[2], hi[3]);
                *(uint4*)(smem + SM_ALO + o) = make_uint4(lo[0], lo[1], lo[2], lo[3]);
            }
        }
        __syncthreads();

#pragma unroll
        for (int ks = 0; ks < 8; ks++) {
            uint32_t whi[4][2], wlo[4][2];
#pragma unroll
            for (int p = 0; p < 2; p++) {
                uint32_t woff = (uint32_t)(w_row + p * 16) * 256 +
                                (uint32_t)(((ks * 2 + w_cbase) ^ l7) << 4);
                uint32_t r[4];
                ldm_x4(r, sbase + SM_WHI + woff);
                whi[p * 2][0] = r[0]; whi[p * 2][1] = r[1];
                whi[p * 2 + 1][0] = r[2]; whi[p * 2 + 1][1] = r[3];
                ldm_x4(r, sbase + SM_WLO + woff);
                wlo[p * 2][0] = r[0]; wlo[p * 2][1] = r[1];
                wlo[p * 2 + 1][0] = r[2]; wlo[p * 2 + 1][1] = r[3];
            }
#pragma unroll
            for (int mi = 0; mi < 2; mi++) {
                uint32_t aoff = (uint32_t)(a_row + mi * 16) * 256 +
                                (uint32_t)(((ks * 2 + a_cbase) ^ l7) << 4);
                uint32_t ah[4], al[4];
                ldm_x4(ah, sbase + SM_AHI + aoff);
                ldm_x4(al, sbase + SM_ALO + aoff);
#pragma unroll
                for (int ni = 0; ni < 4; ni++) {
                    mma_bf16(acc[mi][ni], ah, whi[ni]);
                    mma_bf16(acc[mi][ni], ah, wlo[ni]);
                    mma_bf16(acc[mi][ni], al, whi[ni]);
                }
            }
        }
    }

#pragma unroll
    for (int mi = 0; mi < 2; mi++) {
        int m = m0 + warp_m * 32 + mi * 16 + (lane >> 2);
#pragma unroll
        for (int ni = 0; ni < 4; ni++) {
            int n = warp_n * 32 + ni * 8 + (lane & 3) * 2;
            float b0 = __ldg(&bias[n]);
            float b1 = __ldg(&bias[n + 1]);
            if (m < M) {
                float2 o;
                o.x = fmaxf(fmaf(alpha, acc[mi][ni][0], b0), 0.f);
                o.y = fmaxf(fmaf(alpha, acc[mi][ni][1], b1), 0.f);
                *(float2*)(C + (size_t)m * F + n) = o;
            }
            if (m + 8 < M) {
                float2 o;
                o.x = fmaxf(fmaf(alpha, acc[mi][ni][2], b0), 0.f);
                o.y = fmaxf(fmaf(alpha, acc[mi][ni][3], b1), 0.f);
                *(float2*)(C + (size_t)(m + 8) * F + n) = o;
            }
        }
    }
}

// ============================ classifier head ============================
__global__ void __launch_bounds__(256) head_kernel(const float* __restrict__ p2,
                                                   const float* __restrict__ W,
                                                   const float* __restrict__ b,
                                                   float* __restrict__ out, int M) {
    __shared__ float Ws[8 * F];
    int tid = threadIdx.x;
    *(float4*)&Ws[tid * 4] = *(const float4*)(W + tid * 4);
    __syncthreads();
    int gid = blockIdx.x * 256 + tid;
    int m = gid >> 3;
    int c = gid & 7;
    if (m < M) {
        const float4* row = (const float4*)(p2 + (size_t)m * F);
        const float4* w = (const float4*)&Ws[c * F];
        float acc = 0.0f;
#pragma unroll
        for (int k = 0; k < 32; k++) {
            float4 a = row[k];
            float4 ww = w[k];
            acc = fmaf(a.x, ww.x, fmaf(a.y, ww.y, fmaf(a.z, ww.z, fmaf(a.w, ww.w, acc))));
        }
        out[gid] = acc + b[c];
    }
}

// ============================ launch ============================
extern "C" void kernel_launch(void* const* d_in, const int* in_sizes, int n_in,
                              void* d_out, int out_size) {
    const float* x_p    = (const float*)d_in[0];
    const float* x_a    = (const float*)d_in[1];
    const int*   c_src  = (const int*)d_in[2];
    const int*   c_dst  = (const int*)d_in[3];
    const int*   ao_src = (const int*)d_in[4];
    const int*   ao_dst = (const int*)d_in[5];
    const int*   ha_src = (const int*)d_in[6];
    const int*   ha_dst = (const int*)d_in[7];
    const float* l1c_Wl = (const float*)d_in[8];
    const float* l1c_bl = (const float*)d_in[9];
    const float* l1c_Wr = (const float*)d_in[10];
    const float* l1a_Wl = (const float*)d_in[11];
    const float* l1a_bl = (const float*)d_in[12];
    const float* l1a_Wr = (const float*)d_in[13];
    const float* l1h_Wl = (const float*)d_in[14];
    const float* l1h_bl = (const float*)d_in[15];
    const float* l1h_Wr = (const float*)d_in[16];
    const float* l2c_Wl = (const float*)d_in[17];
    const float* l2c_bl = (const float*)d_in[18];
    const float* l2c_Wr = (const float*)d_in[19];
    const float* l2a_Wl = (const float*)d_in[20];
    const float* l2a_bl = (const float*)d_in[21];
    const float* l2a_Wr = (const float*)d_in[22];
    const float* lin_W  = (const float*)d_in[26];
    const float* lin_b  = (const float*)d_in[27];
    float* out = (float*)d_out;

    const int NP = in_sizes[0] / F;
    const int NA = in_sizes[1] / F;
    const int E  = in_sizes[2];
    const int n3 = 2 * NP + NA;

    float *agg_c, *agg_a, *agg_h, *agg_c2, *agg_a2, *p1, *a1, *p2, *b1, *b2;
    int *cnt3, *rp3, *col3, *part;
    __nv_bfloat16* wblob;
    cudaGetSymbolAddress((void**)&agg_c, g_agg_c);
    cudaGetSymbolAddress((void**)&agg_a, g_agg_a);
    cudaGetSymbolAddress((void**)&agg_h, g_agg_h);
    cudaGetSymbolAddress((void**)&agg_c2, g_agg_c2);
    cudaGetSymbolAddress((void**)&agg_a2, g_agg_a2);
    cudaGetSymbolAddress((void**)&p1, g_p1);
    cudaGetSymbolAddress((void**)&a1, g_a1);
    cudaGetSymbolAddress((void**)&p2, g_p2);
    cudaGetSymbolAddress((void**)&b1, g_b1);
    cudaGetSymbolAddress((void**)&b2, g_b2);
    cudaGetSymbolAddress((void**)&wblob, g_wblob);
    cudaGetSymbolAddress((void**)&cnt3, g_cnt3);
    cudaGetSymbolAddress((void**)&rp3, g_rp3);
    cudaGetSymbolAddress((void**)&col3, g_col3);
    cudaGetSymbolAddress((void**)&part, g_part);

    cudaFuncSetAttribute(gemm_mma<3>, cudaFuncAttributeMaxDynamicSharedMemorySize, SM_TOTAL);
    cudaFuncSetAttribute(gemm_mma<2>, cudaFuncAttributeMaxDynamicSharedMemorySize, SM_TOTAL);

    const int tb = 256;
    const int eb3 = (3 * E + tb - 1) / tb;
    const int nb3 = (n3 + 2047) / 2048;
    const int gb_p = (NP * 32 + tb - 1) / tb;
    const int gb_a = (NA * 32 + tb - 1) / tb;

    auto WB = [&](int m, int half) -> const __nv_bfloat16* {
        return wblob + ((size_t)m * 2 + half) * F * F;
    };

    // ---- second stream + fork/join events (host objects; created per call, no device mem) ----
    cudaStream_t s1;
    cudaStreamCreateWithFlags(&s1, cudaStreamNonBlocking);
    cudaEvent_t evRoot, evPrep, evCSR, evS1;
    cudaEventCreateWithFlags(&evRoot, cudaEventDisableTiming);
    cudaEventCreateWithFlags(&evPrep, cudaEventDisableTiming);
    cudaEventCreateWithFlags(&evCSR, cudaEventDisableTiming);
    cudaEventCreateWithFlags(&evS1, cudaEventDisableTiming);

    // fork s1 from the capture-origin of stream 0
    cudaEventRecord(evRoot, 0);
    cudaStreamWaitEvent(s1, evRoot, 0);

    // ---- s1: weight prep (independent of CSR) ----
    prep_bias_kernel<<<1, 128, 0, s1>>>(l1c_bl, l1a_bl, l2c_bl, l2a_bl);
    W8 w8;
    w8.a[0] = l1c_Wl; w8.b[0] = nullptr;
    w8.a[1] = l1a_Wl; w8.b[1] = nullptr;
    w8.a[2] = l1c_Wr; w8.b[2] = l1a_Wr;    // Wr1 = sum
    w8.a[3] = l1h_Wl; w8.b[3] = nullptr;
    w8.a[4] = l1h_Wr; w8.b[4] = nullptr;
    w8.a[5] = l2c_Wl; w8.b[5] = nullptr;
    w8.a[6] = l2a_Wl; w8.b[6] = nullptr;
    w8.a[7] = l2c_Wr; w8.b[7] = l2a_Wr;    // Wr2 = sum
    prep_w_kernel<<<dim3(8, 8), 256, 0, s1>>>(w8);
    cudaEventRecord(evPrep, s1);

    // ---- s0: fused CSR build ----
    cudaMemsetAsync(cnt3, 0, (size_t)n3 * sizeof(int), 0);
    count3_kernel<<<eb3, tb>>>(c_dst, ao_dst, ha_dst, cnt3, E, NP);
    scanA_kernel<<<nb3, 1024>>>(cnt3, part, n3);
    scanB_kernel<<<1, 128>>>(part, rp3 + n3, nb3);
    scanC_kernel<<<nb3, 1024>>>(cnt3, part, rp3, n3);
    fill3_kernel<<<eb3, tb>>>(c_src, c_dst, ao_src, ao_dst, ha_src, ha_dst,
                              rp3, cnt3, col3, E, NP);
    cudaEventRecord(evCSR, 0);
    cudaStreamWaitEvent(s1, evCSR, 0);

    // ---- s1: author chain (gather_h -> gemm_a1 -> gather2_a) ----
    gather_kernel<<<gb_a, tb, 0, s1>>>(x_p, rp3 + 2 * NP, col3, agg_h, NA);
    {
        GSrc sh{agg_h, WB(3, 0), WB(3, 1)};
        GSrc sxa{x_a, WB(4, 0), WB(4, 1)};
        gemm_mma<2><<<(NA + 63) / 64, 256, SM_TOTAL, s1>>>(sh, sxa, sxa, l1h_bl, 1.0f, a1, NA);
    }
    gather_kernel<<<gb_p, tb, 0, s1>>>(a1, rp3 + NP, col3, agg_a2, NP);
    cudaEventRecord(evS1, s1);

    // ---- s0: patent chain (gather_c + gather_a -> gemm_p1 -> gather2_c) ----
    gather_kernel<<<gb_p, tb>>>(x_p, rp3, col3, agg_c, NP);
    gather_kernel<<<gb_p, tb>>>(x_a, rp3 + NP, col3, agg_a, NP);
    cudaStreamWaitEvent(0, evPrep, 0);
    {
        GSrc sc{agg_c, WB(0, 0), WB(0, 1)};
        GSrc sa{agg_a, WB(1, 0), WB(1, 1)};
        GSrc sx{x_p, WB(2, 0), WB(2, 1)};
        gemm_mma<3><<<(NP + 63) / 64, 256, SM_TOTAL>>>(sc, sa, sx, b1, 0.5f, p1, NP);
    }
    gather_kernel<<<gb_p, tb>>>(p1, rp3, col3, agg_c2, NP);

    // ---- join, then layer-2 GEMM + head on s0 ----
    cudaStreamWaitEvent(0, evS1, 0);
    {
        GSrc sc2{agg_c2, WB(5, 0), WB(5, 1)};
        GSrc sa2{agg_a2, WB(6, 0), WB(6, 1)};
        GSrc sp{p1, WB(7, 0), WB(7, 1)};
        gemm_mma<3><<<(NP + 63) / 64, 256, SM_TOTAL>>>(sc2, sa2, sp, b2, 0.5f, p2, NP);
    }
    head_kernel<<<(NP * 8 + tb - 1) / tb, tb>>>(p2, lin_W, lin_b, out, NP);
}

// round 9
// speedup vs baseline: 2.6883x; 1.1350x over previous
#include <cuda_runtime.h>
#include <cuda_bf16.h>
#include <cstdint>
#include <cstddef>

#define F 128
#define NPMAX 50000
#define NAMAX 100000
#define EMAX 800000
#define N3MAX (2 * NPMAX + NAMAX)

// ============================ helpers ============================
__device__ __forceinline__ uint32_t smem_u32(const void* p) {
    uint32_t a;
    asm("{ .reg .u64 t; cvta.to.shared.u64 t, %1; cvt.u32.u64 %0, t; }" : "=r"(a) : "l"(p));
    return a;
}
__device__ __forceinline__ void ldm_x4(uint32_t* r, uint32_t addr) {
    asm volatile("ldmatrix.sync.aligned.m8n8.x4.shared.b16 {%0,%1,%2,%3}, [%4];"
                 : "=r"(r[0]), "=r"(r[1]), "=r"(r[2]), "=r"(r[3]) : "r"(addr));
}
__device__ __forceinline__ void mma_bf16(float* c, const uint32_t* a, const uint32_t* b) {
    asm volatile(
        "mma.sync.aligned.m16n8k16.row.col.f32.bf16.bf16.f32 "
        "{%0,%1,%2,%3}, {%4,%5,%6,%7}, {%8,%9}, {%0,%1,%2,%3};"
        : "+f"(c[0]), "+f"(c[1]), "+f"(c[2]), "+f"(c[3])
        : "r"(a[0]), "r"(a[1]), "r"(a[2]), "r"(a[3]), "r"(b[0]), "r"(b[1]));
}

// [rows x 128 bf16] tile, 256B/row, 16B chunks, XOR swizzle chunk^(row&7)
__device__ __forceinline__ uint32_t tile_off(int row, int ch) {
    return (uint32_t)(row * 256 + ((ch ^ (row & 7)) << 4));
}

// ============================ device scratch ============================
__device__ float g_agg_c[(size_t)NPMAX * F];
__device__ float g_agg_a[(size_t)NPMAX * F];
__device__ float g_agg_h[(size_t)NAMAX * F];
__device__ float g_agg_c2[(size_t)NPMAX * F];   // layer-2 (separate: overlap WAR safety)
__device__ float g_agg_a2[(size_t)NPMAX * F];
__device__ float g_p1[(size_t)NPMAX * F];
__device__ float g_a1[(size_t)NAMAX * F];
__device__ float g_pbuf[(size_t)NPMAX * F];     // p1 @ Wr2 partial (raw)
__device__ float g_b1[F];
__device__ float g_b2[F];
__device__ __nv_bfloat16 g_wblob[8][2][F * F];  // [matrix][hi/lo][tile-image layout]
// fused CSR over 3 relations: segments [0,NP) c | [NP,2NP) a | [2NP,2NP+NA) h
__device__ int g_cnt3[N3MAX];
__device__ int g_rp3[N3MAX + 1];
__device__ int g_col3[3 * EMAX];
__device__ int g_part[128];

// ============================ fused CSR build ============================
__global__ void count3_kernel(const int* __restrict__ cd, const int* __restrict__ ad,
                              const int* __restrict__ hd, int* __restrict__ cnt3,
                              int E, int NP) {
    int i = blockIdx.x * blockDim.x + threadIdx.x;
    if (i < E) atomicAdd(&cnt3[cd[i]], 1);
    else if (i < 2 * E) atomicAdd(&cnt3[NP + ad[i - E]], 1);
    else if (i < 3 * E) atomicAdd(&cnt3[2 * NP + hd[i - 2 * E]], 1);
}

__global__ void __launch_bounds__(1024) scanA_kernel(const int* __restrict__ cnt,
                                                     int* __restrict__ part, int n) {
    __shared__ int wsum[32];
    int tid = threadIdx.x;
    int base = blockIdx.x * 2048 + tid * 2;
    int v = 0;
    if (base < n) v += cnt[base];
    if (base + 1 < n) v += cnt[base + 1];
#pragma unroll
    for (int o = 16; o; o >>= 1) v += __shfl_down_sync(0xFFFFFFFF, v, o);
    if ((tid & 31) == 0) wsum[tid >> 5] = v;
    __syncthreads();
    if (tid < 32) {
        int x = wsum[tid];
#pragma unroll
        for (int o = 16; o; o >>= 1) x += __shfl_down_sync(0xFFFFFFFF, x, o);
        if (tid == 0) part[blockIdx.x] = x;
    }
}

__global__ void scanB_kernel(int* __restrict__ part, int* __restrict__ rp_end, int nb) {
    __shared__ int ws[4];
    int tid = threadIdx.x;     // 128 threads
    int lane = tid & 31, w = tid >> 5;
    int v = (tid < nb) ? part[tid] : 0;
    int x = v;
#pragma unroll
    for (int o = 1; o < 32; o <<= 1) {
        int y = __shfl_up_sync(0xFFFFFFFF, x, o);
        if (lane >= o) x += y;
    }
    if (lane == 31) ws[w] = x;
    __syncthreads();
    int add = 0;
#pragma unroll
    for (int i = 0; i < 4; i++) add += (i < w) ? ws[i] : 0;
    x += add;
    if (tid < nb) part[tid] = x - v;   // exclusive block offset
    if (tid == 127) *rp_end = x;       // grand total
}

__global__ void __launch_bounds__(1024) scanC_kernel(const int* __restrict__ cnt,
                                                     const int* __restrict__ part,
                                                     int* __restrict__ rp, int n) {
    __shared__ int woff[32];
    int tid = threadIdx.x;
    int lane = tid & 31, w = tid >> 5;
    int base = blockIdx.x * 2048 + tid * 2;
    int e0 = (base < n) ? cnt[base] : 0;
    int e1 = (base + 1 < n) ? cnt[base + 1] : 0;
    int p = e0 + e1;
    int x = p;
#pragma unroll
    for (int o = 1; o < 32; o <<= 1) {
        int y = __shfl_up_sync(0xFFFFFFFF, x, o);
        if (lane >= o) x += y;
    }
    if (lane == 31) woff[w] = x;
    __syncthreads();
    if (tid < 32) {
        int y = woff[tid];
        int z = y;
#pragma unroll
        for (int o = 1; o < 32; o <<= 1) {
            int t = __shfl_up_sync(0xFFFFFFFF, z, o);
            if (tid >= o) z += t;
        }
        woff[tid] = z - y;
    }
    __syncthreads();
    int off = part[blockIdx.x] + woff[w] + x - p;
    if (base < n) rp[base] = off;
    if (base + 1 < n) rp[base + 1] = off + e0;
}

// uses cnt3 as a countdown cursor (fill order within a segment reversed: irrelevant for sums)
__global__ void fill3_kernel(const int* __restrict__ cs, const int* __restrict__ cd,
                             const int* __restrict__ as, const int* __restrict__ ad,
                             const int* __restrict__ hs, const int* __restrict__ hd,
                             const int* __restrict__ rp3, int* __restrict__ cnt3,
                             int* __restrict__ col3, int E, int NP) {
    int i = blockIdx.x * blockDim.x + threadIdx.x;
    int s, d;
    if (i < E) { s = cs[i]; d = cd[i]; }
    else if (i < 2 * E) { s = as[i - E]; d = NP + ad[i - E]; }
    else if (i < 3 * E) { s = hs[i - 2 * E]; d = 2 * NP + hd[i - 2 * E]; }
    else return;
    int p = atomicSub(&cnt3[d], 1) - 1;
    col3[rp3[d] + p] = s;
}

// ============================ CSR mean-gather: warp per dst node, unroll-2 ============================
__global__ void __launch_bounds__(256) gather_kernel(const float* __restrict__ x,
                                                     const int* __restrict__ rp,
                                                     const int* __restrict__ col,
                                                     float* __restrict__ out, int n) {
    int w = (blockIdx.x * blockDim.x + threadIdx.x) >> 5;
    int lane = threadIdx.x & 31;
    if (w >= n) return;
    int s = __ldg(&rp[w]);
    int e = __ldg(&rp[w + 1]);
    float4 acc0 = make_float4(0.f, 0.f, 0.f, 0.f);
    float4 acc1 = make_float4(0.f, 0.f, 0.f, 0.f);
    int i = s;
    for (; i + 2 <= e; i += 2) {
        int c0 = __ldg(&col[i]);
        int c1 = __ldg(&col[i + 1]);
        float4 v0 = *(const float4*)(x + (size_t)c0 * F + lane * 4);
        float4 v1 = *(const float4*)(x + (size_t)c1 * F + lane * 4);
        acc0.x += v0.x; acc0.y += v0.y; acc0.z += v0.z; acc0.w += v0.w;
        acc1.x += v1.x; acc1.y += v1.y; acc1.z += v1.z; acc1.w += v1.w;
    }
    if (i < e) {
        int c = __ldg(&col[i]);
        float4 v = *(const float4*)(x + (size_t)c * F + lane * 4);
        acc0.x += v.x; acc0.y += v.y; acc0.z += v.z; acc0.w += v.w;
    }
    float sc = 1.0f / fmaxf((float)(e - s), 1.0f);
    *(float4*)(out + (size_t)w * F + lane * 4) =
        make_float4((acc0.x + acc1.x) * sc, (acc0.y + acc1.y) * sc,
                    (acc0.z + acc1.z) * sc, (acc0.w + acc1.w) * sc);
}

// ============================ small kernels ============================
__global__ void prep_bias_kernel(const float* __restrict__ b1c, const float* __restrict__ b1a,
                                 const float* __restrict__ b2c, const float* __restrict__ b2a) {
    int i = threadIdx.x;
    if (i < F) {
        g_b1[i] = 0.5f * (b1c[i] + b1a[i]);
        g_b2[i] = 0.5f * (b2c[i] + b2a[i]);
    }
}

struct W8 { const float* a[8]; const float* b[8]; };

__global__ void prep_w_kernel(W8 w) {
    int mat = blockIdx.y;
    int ci = blockIdx.x * 256 + threadIdx.x;   // 0..2047, chunk of 8 elems
    if (ci >= 2048) return;
    int row = ci >> 4, ch = ci & 15;
    const float* pa = w.a[mat];
    const float* pb = w.b[mat];
    int base = row * F + ch * 8;
    uint32_t hi[4], lo[4];
#pragma unroll
    for (int j = 0; j < 4; j++) {
        float x0 = pa[base + 2 * j], x1 = pa[base + 2 * j + 1];
        if (pb) { x0 += pb[base + 2 * j]; x1 += pb[base + 2 * j + 1]; }
        __nv_bfloat16 h0 = __float2bfloat16_rn(x0);
        __nv_bfloat16 h1 = __float2bfloat16_rn(x1);
        __nv_bfloat16 l0 = __float2bfloat16_rn(x0 - __bfloat162float(h0));
        __nv_bfloat16 l1 = __float2bfloat16_rn(x1 - __bfloat162float(h1));
        hi[j] = ((uint32_t)__bfloat16_as_ushort(h1) << 16) | __bfloat16_as_ushort(h0);
        lo[j] = ((uint32_t)__bfloat16_as_ushort(l1) << 16) | __bfloat16_as_ushort(l0);
    }
    uint32_t o = tile_off(row, ch);
    *(uint4*)((char*)&g_wblob[mat][0][0] + o) = make_uint4(hi[0], hi[1], hi[2], hi[3]);
    *(uint4*)((char*)&g_wblob[mat][1][0] + o) = make_uint4(lo[0], lo[1], lo[2], lo[3]);
}

// ============================ mma.sync fused multi-source GEMM (M-tile 64) ============================
// MODE 0: C = relu(alpha*acc + bias)
// MODE 1: C = acc (raw partial, alpha/bias ignored)
// MODE 2: head-fused: o = relu(alpha*(acc + pinit) + bias); out = o @ linW^T + linb. No C store.
// split-bf16: A*W ~= Ahi*Whi + Ahi*Wlo + Alo*Whi, fp32 accumulate
struct GSrc {
    const float* A;
    const __nv_bfloat16* whi;       // tile-image blobs, 32KB each
    const __nv_bfloat16* wlo;
};

#define SM_AHI 0
#define SM_ALO 16384
#define SM_WHI 32768
#define SM_WLO 65536
#define SM_TOTAL 98304

template <int NS, int MODE>
__global__ void __launch_bounds__(256) gemm_mma(GSrc s0, GSrc s1, GSrc s2,
                                                const float* __restrict__ bias,
                                                float alpha, float* __restrict__ C, int M,
                                                const float* __restrict__ pinit,
                                                const float* __restrict__ linW,
                                                const float* __restrict__ linb,
                                                float* __restrict__ hout) {
    extern __shared__ __align__(128) char smem[];
    uint32_t sbase = smem_u32(smem);
    const int tid = threadIdx.x;
    const int wid = tid >> 5;
    const int lane = tid & 31;
    const int warp_m = wid & 1;    // 2 x 32 rows
    const int warp_n = wid >> 1;   // 4 x 32 cols
    const int m0 = blockIdx.x * 64;
    GSrc srcs[3] = {s0, s1, s2};

    float acc[2][4][4];
#pragma unroll
    for (int i = 0; i < 2; i++)
#pragma unroll
        for (int j = 0; j < 4; j++)
#pragma unroll
            for (int k = 0; k < 4; k++) acc[i][j][k] = 0.0f;

    const int a_row = warp_m * 32 + (lane & 15);
    const int a_cbase = (lane >> 4);
    const int w_row = warp_n * 32 + (lane & 7) + ((lane >> 4) << 3);
    const int w_cbase = (lane >> 3) & 1;
    const int l7 = lane & 7;

#pragma unroll
    for (int si = 0; si < NS; si++) {
        __syncthreads();
        {
            const uint4* wh = (const uint4*)srcs[si].whi;
            const uint4* wl = (const uint4*)srcs[si].wlo;
            uint4* dh = (uint4*)(smem + SM_WHI);
            uint4* dl = (uint4*)(smem + SM_WLO);
#pragma unroll
            for (int i = tid; i < 2048; i += 256) { dh[i] = wh[i]; dl[i] = wl[i]; }
        }
        {
            const float* A = srcs[si].A;
#pragma unroll
            for (int ci = tid; ci < 1024; ci += 256) {
                int row = ci >> 4, ch = ci & 15;
                int m = m0 + row;
                float4 v0 = make_float4(0.f, 0.f, 0.f, 0.f), v1 = v0;
                if (m < M) {
                    const float4* g = (const float4*)(A + (size_t)m * F + ch * 8);
                    v0 = g[0]; v1 = g[1];
                }
                float vals[8] = {v0.x, v0.y, v0.z, v0.w, v1.x, v1.y, v1.z, v1.w};
                uint32_t hi[4], lo[4];
#pragma unroll
                for (int j = 0; j < 4; j++) {
                    __nv_bfloat16 h0 = __float2bfloat16_rn(vals[2 * j]);
                    __nv_bfloat16 h1 = __float2bfloat16_rn(vals[2 * j + 1]);
                    __nv_bfloat16 l0 = __float2bfloat16_rn(vals[2 * j] - __bfloat162float(h0));
                    __nv_bfloat16 l1 = __float2bfloat16_rn(vals[2 * j + 1] - __bfloat162float(h1));
                    hi[j] = ((uint32_t)__bfloat16_as_ushort(h1) << 16) | __bfloat16_as_ushort(h0);
                    lo[j] = ((uint32_t)__bfloat16_as_ushort(l1) << 16) | __bfloat16_as_ushort(l0);
                }
                uint32_t o = tile_off(row, ch);
                *(uint4*)(smem + SM_AHI + o) = make_uint4(hi[0], hi[1], hi[2], hi[3]);
                *(uint4*)(smem + SM_ALO + o) = make_uint4(lo[0], lo[1], lo[2], lo[3]);
            }
        }
        __syncthreads();

#pragma unroll
        for (int ks = 0; ks < 8; ks++) {
            uint32_t whi[4][2], wlo[4][2];
#pragma unroll
            for (int p = 0; p < 2; p++) {
                uint32_t woff = (uint32_t)(w_row + p * 16) * 256 +
                                (uint32_t)(((ks * 2 + w_cbase) ^ l7) << 4);
                uint32_t r[4];
                ldm_x4(r, sbase + SM_WHI + woff);
                whi[p * 2][0] = r[0]; whi[p * 2][1] = r[1];
                whi[p * 2 + 1][0] = r[2]; whi[p * 2 + 1][1] = r[3];
                ldm_x4(r, sbase + SM_WLO + woff);
                wlo[p * 2][0] = r[0]; wlo[p * 2][1] = r[1];
                wlo[p * 2 + 1][0] = r[2]; wlo[p * 2 + 1][1] = r[3];
            }
#pragma unroll
            for (int mi = 0; mi < 2; mi++) {
                uint32_t aoff = (uint32_t)(a_row + mi * 16) * 256 +
                                (uint32_t)(((ks * 2 + a_cbase) ^ l7) << 4);
                uint32_t ah[4], al[4];
                ldm_x4(ah, sbase + SM_AHI + aoff);
                ldm_x4(al, sbase + SM_ALO + aoff);
#pragma unroll
                for (int ni = 0; ni < 4; ni++) {
                    mma_bf16(acc[mi][ni], ah, whi[ni]);
                    mma_bf16(acc[mi][ni], ah, wlo[ni]);
                    mma_bf16(acc[mi][ni], al, whi[ni]);
                }
            }
        }
    }

    if (MODE == 0 || MODE == 1) {
#pragma unroll
        for (int mi = 0; mi < 2; mi++) {
            int m = m0 + warp_m * 32 + mi * 16 + (lane >> 2);
#pragma unroll
            for (int ni = 0; ni < 4; ni++) {
                int n = warp_n * 32 + ni * 8 + (lane & 3) * 2;
                float b0 = (MODE == 0) ? __ldg(&bias[n]) : 0.f;
                float b1 = (MODE == 0) ? __ldg(&bias[n + 1]) : 0.f;
                if (m < M) {
                    float2 o;
                    if (MODE == 0) {
                        o.x = fmaxf(fmaf(alpha, acc[mi][ni][0], b0), 0.f);
                        o.y = fmaxf(fmaf(alpha, acc[mi][ni][1], b1), 0.f);
                    } else {
                        o.x = acc[mi][ni][0]; o.y = acc[mi][ni][1];
                    }
                    *(float2*)(C + (size_t)m * F + n) = o;
                }
                if (m + 8 < M) {
                    float2 o;
                    if (MODE == 0) {
                        o.x = fmaxf(fmaf(alpha, acc[mi][ni][2], b0), 0.f);
                        o.y = fmaxf(fmaf(alpha, acc[mi][ni][3], b1), 0.f);
                    } else {
                        o.x = acc[mi][ni][2]; o.y = acc[mi][ni][3];
                    }
                    *(float2*)(C + (size_t)(m + 8) * F + n) = o;
                }
            }
        }
    } else {
        // MODE 2: init-add + relu + fused head
        __syncthreads();
        float* slw = (float*)(smem + SM_WHI);     // reuse: 8x128 linW
        float* shred = (float*)(smem + SM_WLO);   // reuse: [row64][warp_n4][c8]
        for (int i = tid; i < 8 * F; i += 256) slw[i] = linW[i];
        __syncthreads();

        float hp[2][2][8];
#pragma unroll
        for (int a = 0; a < 2; a++)
#pragma unroll
            for (int b = 0; b < 2; b++)
#pragma unroll
                for (int c = 0; c < 8; c++) hp[a][b][c] = 0.f;

#pragma unroll
        for (int mi = 0; mi < 2; mi++) {
            int m = m0 + warp_m * 32 + mi * 16 + (lane >> 2);
#pragma unroll
            for (int ni = 0; ni < 4; ni++) {
                int n = warp_n * 32 + ni * 8 + (lane & 3) * 2;
                float2 pa = *(const float2*)(pinit + (size_t)m * F + n);
                float2 pb = *(const float2*)(pinit + (size_t)(m + 8) * F + n);
                float b0 = __ldg(&bias[n]);
                float b1 = __ldg(&bias[n + 1]);
                float o0 = fmaxf(fmaf(alpha, acc[mi][ni][0] + pa.x, b0), 0.f);
                float o1 = fmaxf(fmaf(alpha, acc[mi][ni][1] + pa.y, b1), 0.f);
                float o2 = fmaxf(fmaf(alpha, acc[mi][ni][2] + pb.x, b0), 0.f);
                float o3 = fmaxf(fmaf(alpha, acc[mi][ni][3] + pb.y, b1), 0.f);
#pragma unroll
                for (int c = 0; c < 8; c++) {
                    float w0 = slw[c * F + n];
                    float w1 = slw[c * F + n + 1];
                    hp[mi][0][c] = fmaf(o0, w0, fmaf(o1, w1, hp[mi][0][c]));
                    hp[mi][1][c] = fmaf(o2, w0, fmaf(o3, w1, hp[mi][1][c]));
                }
            }
        }
        // reduce across the 4 lanes sharing a row (lane&3)
#pragma unroll
        for (int a = 0; a < 2; a++)
#pragma unroll
            for (int b = 0; b < 2; b++)
#pragma unroll
                for (int c = 0; c < 8; c++) {
                    float v = hp[a][b][c];
                    v += __shfl_xor_sync(0xFFFFFFFF, v, 1);
                    v += __shfl_xor_sync(0xFFFFFFFF, v, 2);
                    hp[a][b][c] = v;
                }
        if ((lane & 3) == 0) {
#pragma unroll
            for (int mi = 0; mi < 2; mi++)
#pragma unroll
                for (int h = 0; h < 2; h++) {
                    int rl = warp_m * 32 + mi * 16 + (lane >> 2) + h * 8;
#pragma unroll
                    for (int c = 0; c < 8; c++)
                        shred[rl * 32 + warp_n * 8 + c] = hp[mi][h][c];
                }
        }
        __syncthreads();
#pragma unroll
        for (int idx = tid; idx < 512; idx += 256) {
            int row = idx >> 3, c = idx & 7;
            int m = m0 + row;
            if (m < M) {
                float s = shred[row * 32 + c] + shred[row * 32 + 8 + c] +
                          shred[row * 32 + 16 + c] + shred[row * 32 + 24 + c] + __ldg(&linb[c]);
                hout[(size_t)m * 8 + c] = s;
            }
        }
    }
}

// ============================ launch ============================
extern "C" void kernel_launch(void* const* d_in, const int* in_sizes, int n_in,
                              void* d_out, int out_size) {
    const float* x_p    = (const float*)d_in[0];
    const float* x_a    = (const float*)d_in[1];
    const int*   c_src  = (const int*)d_in[2];
    const int*   c_dst  = (const int*)d_in[3];
    const int*   ao_src = (const int*)d_in[4];
    const int*   ao_dst = (const int*)d_in[5];
    const int*   ha_src = (const int*)d_in[6];
    const int*   ha_dst = (const int*)d_in[7];
    const float* l1c_Wl = (const float*)d_in[8];
    const float* l1c_bl = (const float*)d_in[9];
    const float* l1c_Wr = (const float*)d_in[10];
    const float* l1a_Wl = (const float*)d_in[11];
    const float* l1a_bl = (const float*)d_in[12];
    const float* l1a_Wr = (const float*)d_in[13];
    const float* l1h_Wl = (const float*)d_in[14];
    const float* l1h_bl = (const float*)d_in[15];
    const float* l1h_Wr = (const float*)d_in[16];
    const float* l2c_Wl = (const float*)d_in[17];
    const float* l2c_bl = (const float*)d_in[18];
    const float* l2c_Wr = (const float*)d_in[19];
    const float* l2a_Wl = (const float*)d_in[20];
    const float* l2a_bl = (const float*)d_in[21];
    const float* l2a_Wr = (const float*)d_in[22];
    const float* lin_W  = (const float*)d_in[26];
    const float* lin_b  = (const float*)d_in[27];
    float* out = (float*)d_out;

    const int NP = in_sizes[0] / F;
    const int NA = in_sizes[1] / F;
    const int E  = in_sizes[2];
    const int n3 = 2 * NP + NA;

    float *agg_c, *agg_a, *agg_h, *agg_c2, *agg_a2, *p1, *a1, *pbuf, *b1, *b2;
    int *cnt3, *rp3, *col3, *part;
    __nv_bfloat16* wblob;
    cudaGetSymbolAddress((void**)&agg_c, g_agg_c);
    cudaGetSymbolAddress((void**)&agg_a, g_agg_a);
    cudaGetSymbolAddress((void**)&agg_h, g_agg_h);
    cudaGetSymbolAddress((void**)&agg_c2, g_agg_c2);
    cudaGetSymbolAddress((void**)&agg_a2, g_agg_a2);
    cudaGetSymbolAddress((void**)&p1, g_p1);
    cudaGetSymbolAddress((void**)&a1, g_a1);
    cudaGetSymbolAddress((void**)&pbuf, g_pbuf);
    cudaGetSymbolAddress((void**)&b1, g_b1);
    cudaGetSymbolAddress((void**)&b2, g_b2);
    cudaGetSymbolAddress((void**)&wblob, g_wblob);
    cudaGetSymbolAddress((void**)&cnt3, g_cnt3);
    cudaGetSymbolAddress((void**)&rp3, g_rp3);
    cudaGetSymbolAddress((void**)&col3, g_col3);
    cudaGetSymbolAddress((void**)&part, g_part);

    cudaFuncSetAttribute(gemm_mma<3, 0>, cudaFuncAttributeMaxDynamicSharedMemorySize, SM_TOTAL);
    cudaFuncSetAttribute(gemm_mma<2, 0>, cudaFuncAttributeMaxDynamicSharedMemorySize, SM_TOTAL);
    cudaFuncSetAttribute(gemm_mma<1, 1>, cudaFuncAttributeMaxDynamicSharedMemorySize, SM_TOTAL);
    cudaFuncSetAttribute(gemm_mma<2, 2>, cudaFuncAttributeMaxDynamicSharedMemorySize, SM_TOTAL);

    const int tb = 256;
    const int eb3 = (3 * E + tb - 1) / tb;
    const int nb3 = (n3 + 2047) / 2048;
    const int gb_p = (NP * 32 + tb - 1) / tb;
    const int gb_a = (NA * 32 + tb - 1) / tb;

    auto WB = [&](int m, int half) -> const __nv_bfloat16* {
        return wblob + ((size_t)m * 2 + half) * F * F;
    };

    // ---- second stream + fork/join events (host objects; no device mem) ----
    cudaStream_t s1;
    cudaStreamCreateWithFlags(&s1, cudaStreamNonBlocking);
    cudaEvent_t evRoot, evPrep, evCSR, evP1, evS1;
    cudaEventCreateWithFlags(&evRoot, cudaEventDisableTiming);
    cudaEventCreateWithFlags(&evPrep, cudaEventDisableTiming);
    cudaEventCreateWithFlags(&evCSR, cudaEventDisableTiming);
    cudaEventCreateWithFlags(&evP1, cudaEventDisableTiming);
    cudaEventCreateWithFlags(&evS1, cudaEventDisableTiming);

    cudaEventRecord(evRoot, 0);
    cudaStreamWaitEvent(s1, evRoot, 0);

    // ---- s1: weight prep ----
    prep_bias_kernel<<<1, 128, 0, s1>>>(l1c_bl, l1a_bl, l2c_bl, l2a_bl);
    W8 w8;
    w8.a[0] = l1c_Wl; w8.b[0] = nullptr;
    w8.a[1] = l1a_Wl; w8.b[1] = nullptr;
    w8.a[2] = l1c_Wr; w8.b[2] = l1a_Wr;    // Wr1 = sum
    w8.a[3] = l1h_Wl; w8.b[3] = nullptr;
    w8.a[4] = l1h_Wr; w8.b[4] = nullptr;
    w8.a[5] = l2c_Wl; w8.b[5] = nullptr;
    w8.a[6] = l2a_Wl; w8.b[6] = nullptr;
    w8.a[7] = l2c_Wr; w8.b[7] = l2a_Wr;    // Wr2 = sum
    prep_w_kernel<<<dim3(8, 8), 256, 0, s1>>>(w8);
    cudaEventRecord(evPrep, s1);

    // ---- s0: fused CSR build ----
    cudaMemsetAsync(cnt3, 0, (size_t)n3 * sizeof(int), 0);
    count3_kernel<<<eb3, tb>>>(c_dst, ao_dst, ha_dst, cnt3, E, NP);
    scanA_kernel<<<nb3, 1024>>>(cnt3, part, n3);
    scanB_kernel<<<1, 128>>>(part, rp3 + n3, nb3);
    scanC_kernel<<<nb3, 1024>>>(cnt3, part, rp3, n3);
    fill3_kernel<<<eb3, tb>>>(c_src, c_dst, ao_src, ao_dst, ha_src, ha_dst,
                              rp3, cnt3, col3, E, NP);
    cudaEventRecord(evCSR, 0);
    cudaStreamWaitEvent(s1, evCSR, 0);

    // ---- s1: author chain, then the p1@Wr2 partial ----
    gather_kernel<<<gb_a, tb, 0, s1>>>(x_p, rp3 + 2 * NP, col3, agg_h, NA);
    {
        GSrc sh{agg_h, WB(3, 0), WB(3, 1)};
        GSrc sxa{x_a, WB(4, 0), WB(4, 1)};
        gemm_mma<2, 0><<<(NA + 63) / 64, 256, SM_TOTAL, s1>>>(
            sh, sxa, sxa, l1h_bl, 1.0f, a1, NA, nullptr, nullptr, nullptr, nullptr);
    }
    gather_kernel<<<gb_p, tb, 0, s1>>>(a1, rp3 + NP, col3, agg_a2, NP);
    cudaStreamWaitEvent(s1, evP1, 0);
    {
        GSrc sp{p1, WB(7, 0), WB(7, 1)};
        gemm_mma<1, 1><<<(NP + 63) / 64, 256, SM_TOTAL, s1>>>(
            sp, sp, sp, nullptr, 1.0f, pbuf, NP, nullptr, nullptr, nullptr, nullptr);
    }
    cudaEventRecord(evS1, s1);

    // ---- s0: patent chain ----
    gather_kernel<<<gb_p, tb>>>(x_p, rp3, col3, agg_c, NP);
    gather_kernel<<<gb_p, tb>>>(x_a, rp3 + NP, col3, agg_a, NP);
    cudaStreamWaitEvent(0, evPrep, 0);
    {
        GSrc sc{agg_c, WB(0, 0), WB(0, 1)};
        GSrc sa{agg_a, WB(1, 0), WB(1, 1)};
        GSrc sx{x_p, WB(2, 0), WB(2, 1)};
        gemm_mma<3, 0><<<(NP + 63) / 64, 256, SM_TOTAL>>>(
            sc, sa, sx, b1, 0.5f, p1, NP, nullptr, nullptr, nullptr, nullptr);
    }
    cudaEventRecord(evP1, 0);
    gather_kernel<<<gb_p, tb>>>(p1, rp3, col3, agg_c2, NP);

    // ---- join: final GEMM with init (pbuf) + fused head ----
    cudaStreamWaitEvent(0, evS1, 0);
    {
        GSrc sc2{agg_c2, WB(5, 0), WB(5, 1)};
        GSrc sa2{agg_a2, WB(6, 0), WB(6, 1)};
        gemm_mma<2, 2><<<(NP + 63) / 64, 256, SM_TOTAL>>>(
            sc2, sa2, sa2, b2, 0.5f, nullptr, NP, pbuf, lin_W, lin_b, out);
    }
}